// round 2
// baseline (speedup 1.0000x reference)
#include <cuda_runtime.h>

#define NN    50000
#define EE    800000
#define ET    (EE + NN)        // edges + self loops = 850000
#define INDIM 128
#define HIDC  64
#define H1N   4
#define F1    256              // 4 heads * 64

#define NEG_INF __int_as_float(0xff800000)

// ---------------- scratch (device globals; no allocation allowed) ----------
__device__ __align__(16) float g_h1  [NN * F1];    // x @ W1
__device__ __align__(16) float g_out1[NN * F1];    // layer1 aggregation -> elu in place
__device__ __align__(16) float g_as1 [NN * H1N];
__device__ __align__(16) float g_ad1 [NN * H1N];
__device__ __align__(16) float g_m1  [NN * H1N];
__device__ __align__(16) float g_s1  [NN * H1N];
__device__ __align__(16) float g_e1  [ET * H1N];   // e -> exp(e-m) in place
__device__ __align__(16) float g_g2  [NN * HIDC];  // h2 @ W2
__device__ __align__(16) float g_out2[NN * HIDC];  // layer2 aggregation -> elu in place
__device__ __align__(16) float g_as2 [NN];
__device__ __align__(16) float g_ad2 [NN];
__device__ __align__(16) float g_m2  [NN];
__device__ __align__(16) float g_s2  [NN];
__device__ __align__(16) float g_e2  [ET];
__device__ int g_src[ET];
__device__ int g_dst[ET];
__device__ int g_is64;

// ---------------- helpers ---------------------------------------------------
__device__ __forceinline__ void atomicMaxF(float* addr, float v) {
    if (v >= 0.f) atomicMax((int*)addr, __float_as_int(v));
    else          atomicMin((unsigned int*)addr, __float_as_uint(v));
}

__device__ __forceinline__ void redAdd4(float* addr, float a, float b, float c, float d) {
    asm volatile("red.global.add.v4.f32 [%0], {%1,%2,%3,%4};"
                 :: "l"(addr), "f"(a), "f"(b), "f"(c), "f"(d) : "memory");
}

__device__ __forceinline__ float lrelu02(float x) { return x > 0.f ? x : 0.2f * x; }
__device__ __forceinline__ float eluf(float x)    { return x > 0.f ? x : (__expf(x) - 1.f); }

// ---------------- init ------------------------------------------------------
__global__ void k_init() {
    int i = blockIdx.x * blockDim.x + threadIdx.x;
    int stride = gridDim.x * blockDim.x;
    if (i == 0) g_is64 = 1;
    for (int j = i; j < NN * F1;  j += stride) g_out1[j] = 0.f;
    for (int j = i; j < NN * HIDC; j += stride) g_out2[j] = 0.f;
    for (int j = i; j < NN * H1N; j += stride) { g_m1[j] = NEG_INF; g_s1[j] = 0.f; }
    for (int j = i; j < NN;       j += stride) { g_m2[j] = NEG_INF; g_s2[j] = 0.f; }
}

// int64-vs-int32 edge_index detection: if int64, high words of first E entries are 0
__global__ void k_detect(const unsigned int* __restrict__ w) {
    int i = blockIdx.x * blockDim.x + threadIdx.x;
    if (i < EE) {
        if (w[2 * i + 1] != 0u) g_is64 = 0;
    }
}

__global__ void k_convert(const int* __restrict__ w) {
    int i = blockIdx.x * blockDim.x + threadIdx.x;
    if (i >= ET) return;
    if (i < EE) {
        int s, d;
        if (g_is64) { s = w[2 * i]; d = w[2 * EE + 2 * i]; }
        else        { s = w[i];     d = w[EE + i]; }
        g_src[i] = s; g_dst[i] = d;
    } else {
        g_src[i] = i - EE; g_dst[i] = i - EE;   // self loop
    }
}

// ---------------- register-tiled fp32 GEMM ---------------------------------
template <int BM, int BN, int BK, int TM, int TN>
__device__ __forceinline__ void gemm_body(const float* __restrict__ A,
                                          const float* __restrict__ B,
                                          float* __restrict__ C,
                                          int M, int Nc, int K) {
    __shared__ float As[BK][BM + 1];
    __shared__ float Bs[BK][BN];
    constexpr int TCOLS = BN / TN;
    constexpr int NT = (BM / TM) * (BN / TN);
    const int t = threadIdx.x;
    const int tr = t / TCOLS, tc = t % TCOLS;
    const int m0 = blockIdx.y * BM, n0 = blockIdx.x * BN;
    float acc[TM][TN] = {};
    for (int k0 = 0; k0 < K; k0 += BK) {
        #pragma unroll
        for (int idx = t; idx < BM * BK; idx += NT) {
            int r = idx / BK, c = idx % BK;
            As[c][r] = (m0 + r < M) ? A[(size_t)(m0 + r) * K + k0 + c] : 0.f;
        }
        #pragma unroll
        for (int idx = t; idx < BK * BN; idx += NT) {
            int r = idx / BN, c = idx % BN;
            Bs[r][c] = B[(size_t)(k0 + r) * Nc + n0 + c];
        }
        __syncthreads();
        #pragma unroll
        for (int k = 0; k < BK; k++) {
            float a[TM], b[TN];
            #pragma unroll
            for (int ii = 0; ii < TM; ii++) a[ii] = As[k][tr * TM + ii];
            #pragma unroll
            for (int jj = 0; jj < TN; jj++) b[jj] = Bs[k][tc * TN + jj];
            #pragma unroll
            for (int ii = 0; ii < TM; ii++)
                #pragma unroll
                for (int jj = 0; jj < TN; jj++)
                    acc[ii][jj] += a[ii] * b[jj];
        }
        __syncthreads();
    }
    #pragma unroll
    for (int ii = 0; ii < TM; ii++) {
        int m = m0 + tr * TM + ii;
        if (m < M) {
            #pragma unroll
            for (int jj = 0; jj < TN; jj++)
                C[(size_t)m * Nc + n0 + tc * TN + jj] = acc[ii][jj];
        }
    }
}

__global__ void k_gemm1(const float* __restrict__ x, const float* __restrict__ W1) {
    gemm_body<64, 64, 32, 4, 4>(x, W1, g_h1, NN, F1, INDIM);
}
__global__ void k_gemm2(const float* __restrict__ W2) {
    gemm_body<64, 64, 32, 4, 4>(g_out1, W2, g_g2, NN, HIDC, F1);
}

// ---------------- attention coefficients ------------------------------------
// layer 1: warp per node, 4 heads x 64 channels
__global__ void k_attn1(const float* __restrict__ a_src, const float* __restrict__ a_dst) {
    __shared__ float sa[F1], sd[F1];
    int t = threadIdx.x;                 // 256 threads
    sa[t] = a_src[t]; sd[t] = a_dst[t];
    __syncthreads();
    int w = t >> 5, l = t & 31;
    int n = blockIdx.x * 8 + w;
    if (n >= NN) return;
    const float4* hp = (const float4*)(g_h1 + (size_t)n * F1);
    float ss = 0.f, ds = 0.f;
    #pragma unroll
    for (int q = 0; q < 2; q++) {
        float4 v = hp[l * 2 + q];
        int b = l * 8 + q * 4;
        ss += v.x * sa[b] + v.y * sa[b + 1] + v.z * sa[b + 2] + v.w * sa[b + 3];
        ds += v.x * sd[b] + v.y * sd[b + 1] + v.z * sd[b + 2] + v.w * sd[b + 3];
    }
    // reduce within 8-lane groups (one head per group)
    #pragma unroll
    for (int o = 4; o >= 1; o >>= 1) {
        ss += __shfl_xor_sync(0xFFFFFFFFu, ss, o);
        ds += __shfl_xor_sync(0xFFFFFFFFu, ds, o);
    }
    if ((l & 7) == 0) {
        int h = l >> 3;
        g_as1[n * H1N + h] = ss;
        g_ad1[n * H1N + h] = ds;
    }
}

// layer 2: warp per node, 1 head x 64 channels
__global__ void k_attn2(const float* __restrict__ a_src, const float* __restrict__ a_dst) {
    __shared__ float sa[HIDC], sd[HIDC];
    int t = threadIdx.x;                 // 256 threads
    if (t < HIDC) { sa[t] = a_src[t]; sd[t] = a_dst[t]; }
    __syncthreads();
    int w = t >> 5, l = t & 31;
    int n = blockIdx.x * 8 + w;
    if (n >= NN) return;
    const float2* hp = (const float2*)(g_g2 + (size_t)n * HIDC);
    float2 v = hp[l];
    float ss = v.x * sa[2 * l] + v.y * sa[2 * l + 1];
    float ds = v.x * sd[2 * l] + v.y * sd[2 * l + 1];
    #pragma unroll
    for (int o = 16; o >= 1; o >>= 1) {
        ss += __shfl_xor_sync(0xFFFFFFFFu, ss, o);
        ds += __shfl_xor_sync(0xFFFFFFFFu, ds, o);
    }
    if (l == 0) { g_as2[n] = ss; g_ad2[n] = ds; }
}

// ---------------- edge softmax passes, layer 1 -------------------------------
__global__ void k_edgeA1() {
    int i = blockIdx.x * blockDim.x + threadIdx.x;
    if (i >= ET) return;
    int s = g_src[i], d = g_dst[i];
    float4 a = *(const float4*)&g_as1[s * H1N];
    float4 b = *(const float4*)&g_ad1[d * H1N];
    float4 e;
    e.x = lrelu02(a.x + b.x); e.y = lrelu02(a.y + b.y);
    e.z = lrelu02(a.z + b.z); e.w = lrelu02(a.w + b.w);
    *(float4*)&g_e1[i * H1N] = e;
    atomicMaxF(&g_m1[d * H1N + 0], e.x);
    atomicMaxF(&g_m1[d * H1N + 1], e.y);
    atomicMaxF(&g_m1[d * H1N + 2], e.z);
    atomicMaxF(&g_m1[d * H1N + 3], e.w);
}

__global__ void k_edgeB1() {
    int i = blockIdx.x * blockDim.x + threadIdx.x;
    if (i >= ET) return;
    int d = g_dst[i];
    float4 e = *(const float4*)&g_e1[i * H1N];
    float4 m = *(const float4*)&g_m1[d * H1N];
    float4 ex;
    ex.x = __expf(e.x - m.x); ex.y = __expf(e.y - m.y);
    ex.z = __expf(e.z - m.z); ex.w = __expf(e.w - m.w);
    *(float4*)&g_e1[i * H1N] = ex;
    redAdd4(&g_s1[d * H1N], ex.x, ex.y, ex.z, ex.w);
}

// aggregation: 16 threads per edge, each owns one float4 column (64 floats/head)
__global__ void k_edgeC1() {
    int t = threadIdx.x;                  // 256
    int c4 = t & 15;
    int i = blockIdx.x * 16 + (t >> 4);   // ET divisible by 16... (850000/16=53125)
    int s = g_src[i], d = g_dst[i];
    float4 ex = *(const float4*)&g_e1[i * H1N];      // uniform in group -> broadcast
    float4 sv = *(const float4*)&g_s1[d * H1N];
    float a0 = ex.x / (sv.x + 1e-16f);
    float a1 = ex.y / (sv.y + 1e-16f);
    float a2 = ex.z / (sv.z + 1e-16f);
    float a3 = ex.w / (sv.w + 1e-16f);
    const float4* hs = (const float4*)(g_h1 + (size_t)s * F1);
    float4* od = (float4*)(g_out1 + (size_t)d * F1);
    float4 v;
    v = hs[c4];      redAdd4((float*)&od[c4],      v.x * a0, v.y * a0, v.z * a0, v.w * a0);
    v = hs[16 + c4]; redAdd4((float*)&od[16 + c4], v.x * a1, v.y * a1, v.z * a1, v.w * a1);
    v = hs[32 + c4]; redAdd4((float*)&od[32 + c4], v.x * a2, v.y * a2, v.z * a2, v.w * a2);
    v = hs[48 + c4]; redAdd4((float*)&od[48 + c4], v.x * a3, v.y * a3, v.z * a3, v.w * a3);
}

// ---------------- edge softmax passes, layer 2 -------------------------------
__global__ void k_edgeA2() {
    int i = blockIdx.x * blockDim.x + threadIdx.x;
    if (i >= ET) return;
    int s = g_src[i], d = g_dst[i];
    float e = lrelu02(g_as2[s] + g_ad2[d]);
    g_e2[i] = e;
    atomicMaxF(&g_m2[d], e);
}

__global__ void k_edgeB2() {
    int i = blockIdx.x * blockDim.x + threadIdx.x;
    if (i >= ET) return;
    int d = g_dst[i];
    float ex = __expf(g_e2[i] - g_m2[d]);
    g_e2[i] = ex;
    atomicAdd(&g_s2[d], ex);
}

__global__ void k_edgeC2() {
    int t = threadIdx.x;                  // 256
    int c4 = t & 15;
    int i = blockIdx.x * 16 + (t >> 4);
    int s = g_src[i], d = g_dst[i];
    float alpha = g_e2[i] / (g_s2[d] + 1e-16f);
    float4 v = ((const float4*)(g_g2 + (size_t)s * HIDC))[c4];
    redAdd4(g_out2 + (size_t)d * HIDC + c4 * 4,
            v.x * alpha, v.y * alpha, v.z * alpha, v.w * alpha);
}

// ---------------- bias + ELU -------------------------------------------------
__global__ void k_fin1(const float* __restrict__ b1) {
    int i = blockIdx.x * blockDim.x + threadIdx.x;
    if (i >= NN * F1) return;
    g_out1[i] = eluf(g_out1[i] + b1[i & (F1 - 1)]);
}

__global__ void k_fin2(const float* __restrict__ b2) {
    int i = blockIdx.x * blockDim.x + threadIdx.x;
    if (i >= NN * HIDC) return;
    g_out2[i] = eluf(g_out2[i] + b2[i & (HIDC - 1)]);
}

// ---------------- classifier MLP: relu(z@W3+b3)@W4+b4 ------------------------
__global__ void k_mlp(const float* __restrict__ W3, const float* __restrict__ b3,
                      const float* __restrict__ W4, const float* __restrict__ b4,
                      float* __restrict__ out) {
    __shared__ float sW3[64 * 32];
    __shared__ float sb3[32];
    __shared__ float sW4[32 * 2];
    __shared__ float sb4[2];
    __shared__ float sz[32][65];
    __shared__ float sh[32][33];
    int t = threadIdx.x;                  // 128 threads, 32 nodes per block
    for (int j = t; j < 2048; j += 128) sW3[j] = W3[j];
    if (t < 32) sb3[t] = b3[t];
    if (t < 64) sW4[t] = W4[t];
    if (t < 2)  sb4[t] = b4[t];
    int n0 = blockIdx.x * 32;
    for (int j = t; j < 2048; j += 128) {
        int r = j >> 6, c = j & 63;
        int n = n0 + r;
        sz[r][c] = (n < NN) ? g_out2[(size_t)n * HIDC + c] : 0.f;
    }
    __syncthreads();
    for (int j = t; j < 1024; j += 128) {
        int r = j >> 5, hh = j & 31;
        float acc = sb3[hh];
        #pragma unroll
        for (int k = 0; k < 64; k++) acc += sz[r][k] * sW3[k * 32 + hh];
        sh[r][hh] = fmaxf(acc, 0.f);
    }
    __syncthreads();
    if (t < 64) {
        int r = t >> 1, o = t & 1;
        int n = n0 + r;
        if (n < NN) {
            float acc = sb4[o];
            #pragma unroll
            for (int k = 0; k < 32; k++) acc += sh[r][k] * sW4[k * 2 + o];
            out[(size_t)n * 2 + o] = acc;
        }
    }
}

// ---------------- launch -----------------------------------------------------
extern "C" void kernel_launch(void* const* d_in, const int* in_sizes, int n_in,
                              void* d_out, int out_size) {
    const float* x       = (const float*)d_in[0];
    const void*  eidx    = d_in[1];
    const float* W1      = (const float*)d_in[2];
    const float* a_src1  = (const float*)d_in[3];
    const float* a_dst1  = (const float*)d_in[4];
    const float* b1      = (const float*)d_in[5];
    const float* W2      = (const float*)d_in[6];
    const float* a_src2  = (const float*)d_in[7];
    const float* a_dst2  = (const float*)d_in[8];
    const float* b2      = (const float*)d_in[9];
    const float* W3      = (const float*)d_in[10];
    const float* b3      = (const float*)d_in[11];
    const float* W4      = (const float*)d_in[12];
    const float* b4      = (const float*)d_in[13];
    float* out = (float*)d_out;

    k_init<<<2048, 256>>>();
    k_detect<<<(EE + 255) / 256, 256>>>((const unsigned int*)eidx);
    k_convert<<<(ET + 255) / 256, 256>>>((const int*)eidx);

    // layer 1
    k_gemm1<<<dim3(F1 / 64, (NN + 63) / 64), 256>>>(x, W1);
    k_attn1<<<(NN + 7) / 8, 256>>>(a_src1, a_dst1);
    k_edgeA1<<<(ET + 255) / 256, 256>>>();
    k_edgeB1<<<(ET + 255) / 256, 256>>>();
    k_edgeC1<<<(ET + 15) / 16, 256>>>();
    k_fin1<<<(NN * F1 + 255) / 256, 256>>>(b1);

    // layer 2
    k_gemm2<<<dim3(HIDC / 64, (NN + 63) / 64), 256>>>(W2);
    k_attn2<<<(NN + 7) / 8, 256>>>(a_src2, a_dst2);
    k_edgeA2<<<(ET + 255) / 256, 256>>>();
    k_edgeB2<<<(ET + 255) / 256, 256>>>();
    k_edgeC2<<<(ET + 15) / 16, 256>>>();
    k_fin2<<<(NN * HIDC + 255) / 256, 256>>>(b2);

    // classifier
    k_mlp<<<(NN + 31) / 32, 128>>>(W3, b3, W4, b4, out);
}

// round 3
// speedup vs baseline: 1.3073x; 1.3073x over previous
#include <cuda_runtime.h>

#define NN    50000
#define EE    800000
#define ET    (EE + NN)        // edges + self loops = 850000
#define INDIM 128
#define HIDC  64
#define H1N   4
#define F1    256              // 4 heads * 64

#define NEG_INF __int_as_float(0xff800000)

// ---------------- scratch (device globals; no allocation allowed) ----------
__device__ __align__(16) float g_h1  [NN * F1];    // x @ W1
__device__ __align__(16) float g_out1[NN * F1];    // layer1 aggregation (raw sums)
__device__ __align__(16) float g_as1 [NN * H1N];
__device__ __align__(16) float g_ad1 [NN * H1N];
__device__ __align__(16) float g_m1  [NN * H1N];
__device__ __align__(16) float g_s1  [NN * H1N];
__device__ __align__(16) float g_e1  [ET * H1N];   // e -> exp(e-m) in place
__device__ __align__(16) float g_g2  [NN * HIDC];  // elu(out1+b1) @ W2
__device__ __align__(16) float g_out2[NN * HIDC];  // layer2 aggregation (raw sums)
__device__ __align__(16) float g_as2 [NN];
__device__ __align__(16) float g_ad2 [NN];
__device__ __align__(16) float g_m2  [NN];
__device__ __align__(16) float g_s2  [NN];
__device__ __align__(16) float g_e2  [ET];
__device__ int g_src[ET];
__device__ int g_dst[ET];
__device__ int g_is64;

// ---------------- helpers ---------------------------------------------------
__device__ __forceinline__ void atomicMaxF(float* addr, float v) {
    if (v >= 0.f) atomicMax((int*)addr, __float_as_int(v));
    else          atomicMin((unsigned int*)addr, __float_as_uint(v));
}

__device__ __forceinline__ void redAdd4(float* addr, float a, float b, float c, float d) {
    asm volatile("red.global.add.v4.f32 [%0], {%1,%2,%3,%4};"
                 :: "l"(addr), "f"(a), "f"(b), "f"(c), "f"(d) : "memory");
}

__device__ __forceinline__ float lrelu02(float x) { return x > 0.f ? x : 0.2f * x; }
__device__ __forceinline__ float eluf(float x)    { return x > 0.f ? x : (__expf(x) - 1.f); }

// ---------------- init ------------------------------------------------------
__global__ void k_init() {
    int i = blockIdx.x * blockDim.x + threadIdx.x;
    int stride = gridDim.x * blockDim.x;
    if (i == 0) g_is64 = 1;
    for (int j = i; j < NN * F1;  j += stride) g_out1[j] = 0.f;
    for (int j = i; j < NN * HIDC; j += stride) g_out2[j] = 0.f;
    for (int j = i; j < NN * H1N; j += stride) { g_m1[j] = NEG_INF; g_s1[j] = 0.f; }
    for (int j = i; j < NN;       j += stride) { g_m2[j] = NEG_INF; g_s2[j] = 0.f; }
}

// int64-vs-int32 edge_index detection: if int64, high words of first E entries are 0
__global__ void k_detect(const unsigned int* __restrict__ w) {
    int i = blockIdx.x * blockDim.x + threadIdx.x;
    if (i < EE) {
        if (w[2 * i + 1] != 0u) g_is64 = 0;
    }
}

__global__ void k_convert(const int* __restrict__ w) {
    int i = blockIdx.x * blockDim.x + threadIdx.x;
    if (i >= ET) return;
    if (i < EE) {
        int s, d;
        if (g_is64) { s = w[2 * i]; d = w[2 * EE + 2 * i]; }
        else        { s = w[i];     d = w[EE + i]; }
        g_src[i] = s; g_dst[i] = d;
    } else {
        g_src[i] = i - EE; g_dst[i] = i - EE;   // self loop
    }
}

// ---------------- double-buffered register-tiled fp32 GEMM -------------------
// BM=128, BN=64, BK=16, 256 threads, 8x4 per thread.
// ACT: apply elu(a + bias[kcol]) to A elements on load (fuses prior bias+ELU).
template <bool ACT>
__device__ __forceinline__ void gemm_body(const float* __restrict__ A,
                                          const float* __restrict__ B,
                                          float* __restrict__ C,
                                          int M, int Nc, int K,
                                          const float* __restrict__ bias) {
    constexpr int BM = 128, BN = 64, BK = 16, TM = 8, TN = 4;
    __shared__ float As[2][BK][BM + 4];
    __shared__ float Bs[2][BK][BN];
    const int t  = threadIdx.x;
    const int tr = t >> 4;            // 0..15
    const int tc = t & 15;            // 0..15
    const int m0 = blockIdx.y * BM, n0 = blockIdx.x * BN;

    // A staging: thread covers idx = 2t, 2t+1; row = idx/4 (0..127), kq = (idx%4)*4
    const int ar0 = (2 * t) / 4,     ak0 = ((2 * t)     & 3) * 4;
    const int ar1 = (2 * t + 1) / 4, ak1 = ((2 * t + 1) & 3) * 4;
    // B staging: row k = t/16, col = (t%16)*4
    const int bk = t >> 4, bc = (t & 15) * 4;

    float acc[TM][TN] = {};
    float4 av0, av1, bv;
    const int KT = K / BK;

    auto ldA = [&](int k0, int row, int kq) -> float4 {
        int m = m0 + row;
        float4 v = make_float4(0.f, 0.f, 0.f, 0.f);
        if (m < M) {
            v = *(const float4*)&A[(size_t)m * K + k0 + kq];
            if (ACT) {
                int kc = k0 + kq;
                v.x = eluf(v.x + bias[kc]);
                v.y = eluf(v.y + bias[kc + 1]);
                v.z = eluf(v.z + bias[kc + 2]);
                v.w = eluf(v.w + bias[kc + 3]);
            }
        }
        return v;
    };

    // prologue: tile 0 -> buffer 0
    av0 = ldA(0, ar0, ak0);
    av1 = ldA(0, ar1, ak1);
    bv  = *(const float4*)&B[(size_t)bk * Nc + n0 + bc];
    As[0][ak0 + 0][ar0] = av0.x; As[0][ak0 + 1][ar0] = av0.y;
    As[0][ak0 + 2][ar0] = av0.z; As[0][ak0 + 3][ar0] = av0.w;
    As[0][ak1 + 0][ar1] = av1.x; As[0][ak1 + 1][ar1] = av1.y;
    As[0][ak1 + 2][ar1] = av1.z; As[0][ak1 + 3][ar1] = av1.w;
    *(float4*)&Bs[0][bk][bc] = bv;
    __syncthreads();

    int buf = 0;
    for (int kt = 0; kt < KT; kt++) {
        const bool next = (kt + 1 < KT);
        if (next) {
            int k0 = (kt + 1) * BK;
            av0 = ldA(k0, ar0, ak0);
            av1 = ldA(k0, ar1, ak1);
            bv  = *(const float4*)&B[(size_t)(k0 + bk) * Nc + n0 + bc];
        }
        #pragma unroll
        for (int k = 0; k < BK; k++) {
            float a[TM], b[TN];
            #pragma unroll
            for (int ii = 0; ii < TM; ii++) a[ii] = As[buf][k][tr * TM + ii];
            #pragma unroll
            for (int jj = 0; jj < TN; jj++) b[jj] = Bs[buf][k][tc * TN + jj];
            #pragma unroll
            for (int ii = 0; ii < TM; ii++)
                #pragma unroll
                for (int jj = 0; jj < TN; jj++)
                    acc[ii][jj] = fmaf(a[ii], b[jj], acc[ii][jj]);
        }
        if (next) {
            int nb = buf ^ 1;
            As[nb][ak0 + 0][ar0] = av0.x; As[nb][ak0 + 1][ar0] = av0.y;
            As[nb][ak0 + 2][ar0] = av0.z; As[nb][ak0 + 3][ar0] = av0.w;
            As[nb][ak1 + 0][ar1] = av1.x; As[nb][ak1 + 1][ar1] = av1.y;
            As[nb][ak1 + 2][ar1] = av1.z; As[nb][ak1 + 3][ar1] = av1.w;
            *(float4*)&Bs[nb][bk][bc] = bv;
        }
        __syncthreads();
        buf ^= 1;
    }

    #pragma unroll
    for (int ii = 0; ii < TM; ii++) {
        int m = m0 + tr * TM + ii;
        if (m < M) {
            float4 o = make_float4(acc[ii][0], acc[ii][1], acc[ii][2], acc[ii][3]);
            *(float4*)&C[(size_t)m * Nc + n0 + tc * TN] = o;
        }
    }
}

__global__ void __launch_bounds__(256) k_gemm1(const float* __restrict__ x,
                                               const float* __restrict__ W1) {
    gemm_body<false>(x, W1, g_h1, NN, F1, INDIM, nullptr);
}
// A = elu(g_out1 + b1) fused on load
__global__ void __launch_bounds__(256) k_gemm2(const float* __restrict__ W2,
                                               const float* __restrict__ b1) {
    gemm_body<true>(g_out1, W2, g_g2, NN, HIDC, F1, b1);
}

// ---------------- attention coefficients ------------------------------------
// layer 1: warp per node, 4 heads x 64 channels
__global__ void k_attn1(const float* __restrict__ a_src, const float* __restrict__ a_dst) {
    __shared__ float sa[F1], sd[F1];
    int t = threadIdx.x;                 // 256 threads
    sa[t] = a_src[t]; sd[t] = a_dst[t];
    __syncthreads();
    int w = t >> 5, l = t & 31;
    int n = blockIdx.x * 8 + w;
    if (n >= NN) return;
    const float4* hp = (const float4*)(g_h1 + (size_t)n * F1);
    float ss = 0.f, ds = 0.f;
    #pragma unroll
    for (int q = 0; q < 2; q++) {
        float4 v = hp[l * 2 + q];
        int b = l * 8 + q * 4;
        ss += v.x * sa[b] + v.y * sa[b + 1] + v.z * sa[b + 2] + v.w * sa[b + 3];
        ds += v.x * sd[b] + v.y * sd[b + 1] + v.z * sd[b + 2] + v.w * sd[b + 3];
    }
    #pragma unroll
    for (int o = 4; o >= 1; o >>= 1) {
        ss += __shfl_xor_sync(0xFFFFFFFFu, ss, o);
        ds += __shfl_xor_sync(0xFFFFFFFFu, ds, o);
    }
    if ((l & 7) == 0) {
        int h = l >> 3;
        g_as1[n * H1N + h] = ss;
        g_ad1[n * H1N + h] = ds;
    }
}

// layer 2: warp per node, 1 head x 64 channels
__global__ void k_attn2(const float* __restrict__ a_src, const float* __restrict__ a_dst) {
    __shared__ float sa[HIDC], sd[HIDC];
    int t = threadIdx.x;                 // 256 threads
    if (t < HIDC) { sa[t] = a_src[t]; sd[t] = a_dst[t]; }
    __syncthreads();
    int w = t >> 5, l = t & 31;
    int n = blockIdx.x * 8 + w;
    if (n >= NN) return;
    const float2* hp = (const float2*)(g_g2 + (size_t)n * HIDC);
    float2 v = hp[l];
    float ss = v.x * sa[2 * l] + v.y * sa[2 * l + 1];
    float ds = v.x * sd[2 * l] + v.y * sd[2 * l + 1];
    #pragma unroll
    for (int o = 16; o >= 1; o >>= 1) {
        ss += __shfl_xor_sync(0xFFFFFFFFu, ss, o);
        ds += __shfl_xor_sync(0xFFFFFFFFu, ds, o);
    }
    if (l == 0) { g_as2[n] = ss; g_ad2[n] = ds; }
}

// ---------------- edge softmax passes, layer 1 -------------------------------
__global__ void k_edgeA1() {
    int i = blockIdx.x * blockDim.x + threadIdx.x;
    if (i >= ET) return;
    int s = g_src[i], d = g_dst[i];
    float4 a = *(const float4*)&g_as1[s * H1N];
    float4 b = *(const float4*)&g_ad1[d * H1N];
    float4 e;
    e.x = lrelu02(a.x + b.x); e.y = lrelu02(a.y + b.y);
    e.z = lrelu02(a.z + b.z); e.w = lrelu02(a.w + b.w);
    *(float4*)&g_e1[i * H1N] = e;
    atomicMaxF(&g_m1[d * H1N + 0], e.x);
    atomicMaxF(&g_m1[d * H1N + 1], e.y);
    atomicMaxF(&g_m1[d * H1N + 2], e.z);
    atomicMaxF(&g_m1[d * H1N + 3], e.w);
}

__global__ void k_edgeB1() {
    int i = blockIdx.x * blockDim.x + threadIdx.x;
    if (i >= ET) return;
    int d = g_dst[i];
    float4 e = *(const float4*)&g_e1[i * H1N];
    float4 m = *(const float4*)&g_m1[d * H1N];
    float4 ex;
    ex.x = __expf(e.x - m.x); ex.y = __expf(e.y - m.y);
    ex.z = __expf(e.z - m.z); ex.w = __expf(e.w - m.w);
    *(float4*)&g_e1[i * H1N] = ex;
    redAdd4(&g_s1[d * H1N], ex.x, ex.y, ex.z, ex.w);
}

// aggregation: 16 threads per edge, each owns one float4 column (64 floats/head)
__global__ void k_edgeC1() {
    int t = threadIdx.x;                  // 256
    int c4 = t & 15;
    int i = blockIdx.x * 16 + (t >> 4);
    int s = g_src[i], d = g_dst[i];
    float4 ex = *(const float4*)&g_e1[i * H1N];
    float4 sv = *(const float4*)&g_s1[d * H1N];
    float a0 = ex.x / (sv.x + 1e-16f);
    float a1 = ex.y / (sv.y + 1e-16f);
    float a2 = ex.z / (sv.z + 1e-16f);
    float a3 = ex.w / (sv.w + 1e-16f);
    const float4* hs = (const float4*)(g_h1 + (size_t)s * F1);
    float4* od = (float4*)(g_out1 + (size_t)d * F1);
    float4 v;
    v = hs[c4];      redAdd4((float*)&od[c4],      v.x * a0, v.y * a0, v.z * a0, v.w * a0);
    v = hs[16 + c4]; redAdd4((float*)&od[16 + c4], v.x * a1, v.y * a1, v.z * a1, v.w * a1);
    v = hs[32 + c4]; redAdd4((float*)&od[32 + c4], v.x * a2, v.y * a2, v.z * a2, v.w * a2);
    v = hs[48 + c4]; redAdd4((float*)&od[48 + c4], v.x * a3, v.y * a3, v.z * a3, v.w * a3);
}

// ---------------- edge softmax passes, layer 2 -------------------------------
__global__ void k_edgeA2() {
    int i = blockIdx.x * blockDim.x + threadIdx.x;
    if (i >= ET) return;
    int s = g_src[i], d = g_dst[i];
    float e = lrelu02(g_as2[s] + g_ad2[d]);
    g_e2[i] = e;
    atomicMaxF(&g_m2[d], e);
}

__global__ void k_edgeB2() {
    int i = blockIdx.x * blockDim.x + threadIdx.x;
    if (i >= ET) return;
    int d = g_dst[i];
    float ex = __expf(g_e2[i] - g_m2[d]);
    g_e2[i] = ex;
    atomicAdd(&g_s2[d], ex);
}

__global__ void k_edgeC2() {
    int t = threadIdx.x;                  // 256
    int c4 = t & 15;
    int i = blockIdx.x * 16 + (t >> 4);
    int s = g_src[i], d = g_dst[i];
    float alpha = g_e2[i] / (g_s2[d] + 1e-16f);
    float4 v = ((const float4*)(g_g2 + (size_t)s * HIDC))[c4];
    redAdd4(g_out2 + (size_t)d * HIDC + c4 * 4,
            v.x * alpha, v.y * alpha, v.z * alpha, v.w * alpha);
}

// ---------------- classifier MLP: relu(elu(z+b2)@W3+b3)@W4+b4 ---------------
__global__ void k_mlp(const float* __restrict__ b2,
                      const float* __restrict__ W3, const float* __restrict__ b3,
                      const float* __restrict__ W4, const float* __restrict__ b4,
                      float* __restrict__ out) {
    __shared__ float sW3[64 * 32];
    __shared__ float sb3[32];
    __shared__ float sW4[32 * 2];
    __shared__ float sb4[2];
    __shared__ float sb2[64];
    __shared__ float sz[32][65];
    __shared__ float sh[32][33];
    int t = threadIdx.x;                  // 128 threads, 32 nodes per block
    for (int j = t; j < 2048; j += 128) sW3[j] = W3[j];
    if (t < 32) sb3[t] = b3[t];
    if (t < 64) { sW4[t] = W4[t]; sb2[t] = b2[t]; }
    if (t < 2)  sb4[t] = b4[t];
    __syncthreads();
    int n0 = blockIdx.x * 32;
    for (int j = t; j < 2048; j += 128) {
        int r = j >> 6, c = j & 63;
        int n = n0 + r;
        sz[r][c] = (n < NN) ? eluf(g_out2[(size_t)n * HIDC + c] + sb2[c]) : 0.f;
    }
    __syncthreads();
    for (int j = t; j < 1024; j += 128) {
        int r = j >> 5, hh = j & 31;
        float acc = sb3[hh];
        #pragma unroll
        for (int k = 0; k < 64; k++) acc += sz[r][k] * sW3[k * 32 + hh];
        sh[r][hh] = fmaxf(acc, 0.f);
    }
    __syncthreads();
    if (t < 64) {
        int r = t >> 1, o = t & 1;
        int n = n0 + r;
        if (n < NN) {
            float acc = sb4[o];
            #pragma unroll
            for (int k = 0; k < 32; k++) acc += sh[r][k] * sW4[k * 2 + o];
            out[(size_t)n * 2 + o] = acc;
        }
    }
}

// ---------------- launch -----------------------------------------------------
extern "C" void kernel_launch(void* const* d_in, const int* in_sizes, int n_in,
                              void* d_out, int out_size) {
    const float* x       = (const float*)d_in[0];
    const void*  eidx    = d_in[1];
    const float* W1      = (const float*)d_in[2];
    const float* a_src1  = (const float*)d_in[3];
    const float* a_dst1  = (const float*)d_in[4];
    const float* b1      = (const float*)d_in[5];
    const float* W2      = (const float*)d_in[6];
    const float* a_src2  = (const float*)d_in[7];
    const float* a_dst2  = (const float*)d_in[8];
    const float* b2      = (const float*)d_in[9];
    const float* W3      = (const float*)d_in[10];
    const float* b3      = (const float*)d_in[11];
    const float* W4      = (const float*)d_in[12];
    const float* b4      = (const float*)d_in[13];
    float* out = (float*)d_out;

    k_init<<<2048, 256>>>();
    k_detect<<<(EE + 255) / 256, 256>>>((const unsigned int*)eidx);
    k_convert<<<(ET + 255) / 256, 256>>>((const int*)eidx);

    // layer 1
    k_gemm1<<<dim3(F1 / 64, (NN + 127) / 128), 256>>>(x, W1);
    k_attn1<<<(NN + 7) / 8, 256>>>(a_src1, a_dst1);
    k_edgeA1<<<(ET + 255) / 256, 256>>>();
    k_edgeB1<<<(ET + 255) / 256, 256>>>();
    k_edgeC1<<<(ET + 15) / 16, 256>>>();

    // layer 2 (bias+ELU of layer1 fused into gemm2's A load)
    k_gemm2<<<dim3(HIDC / 64, (NN + 127) / 128), 256>>>(W2, b1);
    k_attn2<<<(NN + 7) / 8, 256>>>(a_src2, a_dst2);
    k_edgeA2<<<(ET + 255) / 256, 256>>>();
    k_edgeB2<<<(ET + 255) / 256, 256>>>();
    k_edgeC2<<<(ET + 15) / 16, 256>>>();

    // classifier (bias+ELU of layer2 fused into MLP input load)
    k_mlp<<<(NN + 31) / 32, 128>>>(b2, W3, b3, W4, b4, out);
}

// round 5
// speedup vs baseline: 1.4004x; 1.0712x over previous
#include <cuda_runtime.h>

#define NN    50000
#define EE    800000
#define ET    (EE + NN)        // edges + self loops = 850000
#define INDIM 128
#define HIDC  64
#define H1N   4
#define F1    256              // 4 heads * 64

// ---------------- scratch (device globals; no allocation allowed) ----------
__device__ __align__(16) float g_h1  [NN * F1];    // x @ W1
__device__ __align__(16) float g_out1[NN * F1];    // layer1 aggregation (raw sums)
__device__ __align__(16) float g_as1 [NN * H1N];
__device__ __align__(16) float g_ad1 [NN * H1N];
__device__ __align__(16) float g_s1  [NN * H1N];
__device__ __align__(16) float g_e1  [ET * H1N];   // exp(e) per edge
__device__ __align__(16) float g_g2  [NN * HIDC];  // elu(out1+b1) @ W2
__device__ __align__(16) float g_out2[NN * HIDC];  // layer2 aggregation (raw sums)
__device__ __align__(16) float g_as2 [NN];
__device__ __align__(16) float g_ad2 [NN];
__device__ __align__(16) float g_s2  [NN];
__device__ __align__(16) float g_e2  [ET];
__device__ int g_src[ET];
__device__ int g_dst[ET];
__device__ int g_is64;

// ---------------- helpers ---------------------------------------------------
__device__ __forceinline__ void redAdd4(float* addr, float a, float b, float c, float d) {
    asm volatile("red.global.add.v4.f32 [%0], {%1,%2,%3,%4};"
                 :: "l"(addr), "f"(a), "f"(b), "f"(c), "f"(d) : "memory");
}

__device__ __forceinline__ float lrelu02(float x) { return x > 0.f ? x : 0.2f * x; }
__device__ __forceinline__ float eluf(float x)    { return x > 0.f ? x : (__expf(x) - 1.f); }

// ---------------- init ------------------------------------------------------
__global__ void k_init() {
    int i = blockIdx.x * blockDim.x + threadIdx.x;
    int stride = gridDim.x * blockDim.x;
    if (i == 0) g_is64 = 1;
    for (int j = i; j < NN * F1;   j += stride) g_out1[j] = 0.f;
    for (int j = i; j < NN * HIDC; j += stride) g_out2[j] = 0.f;
    for (int j = i; j < NN * H1N;  j += stride) g_s1[j] = 0.f;
    for (int j = i; j < NN;        j += stride) g_s2[j] = 0.f;
}

// int64-vs-int32 edge_index detection: if int64, high words of first E entries are 0
__global__ void k_detect(const unsigned int* __restrict__ w) {
    int i = blockIdx.x * blockDim.x + threadIdx.x;
    if (i < EE) {
        if (w[2 * i + 1] != 0u) g_is64 = 0;
    }
}

__global__ void k_convert(const int* __restrict__ w) {
    int i = blockIdx.x * blockDim.x + threadIdx.x;
    if (i >= ET) return;
    if (i < EE) {
        int s, d;
        if (g_is64) { s = w[2 * i]; d = w[2 * EE + 2 * i]; }
        else        { s = w[i];     d = w[EE + i]; }
        g_src[i] = s; g_dst[i] = d;
    } else {
        g_src[i] = i - EE; g_dst[i] = i - EE;   // self loop
    }
}

// ---------------- double-buffered register-tiled fp32 GEMM -------------------
// BM=128, BK=16, TM=8, 256 threads. BN/TN templated (128/8 or 64/4).
// ACT: apply elu(a + bias[kcol]) to A elements on load.
template <int BN, int TN, bool ACT>
__device__ __forceinline__ void gemm_body(const float* __restrict__ A,
                                          const float* __restrict__ B,
                                          float* __restrict__ C,
                                          int M, int Nc, int K,
                                          const float* __restrict__ bias) {
    constexpr int BM = 128, BK = 16, TM = 8;
    constexpr int NB4 = (BK * BN / 4) / 256;   // B float4 loads per thread (2 or 1)
    __shared__ float As[2][BK][BM + 4];
    __shared__ float Bs[2][BK][BN];
    const int t  = threadIdx.x;
    const int tr = t >> 4;            // 0..15
    const int tc = t & 15;            // 0..15
    const int m0 = blockIdx.y * BM, n0 = blockIdx.x * BN;

    // A staging: thread covers idx = 2t, 2t+1; row = idx/4 (0..127), kq = (idx%4)*4
    const int ar0 = (2 * t) / 4,     ak0 = ((2 * t)     & 3) * 4;
    const int ar1 = (2 * t + 1) / 4, ak1 = ((2 * t + 1) & 3) * 4;

    float acc[TM][TN] = {};
    float4 av0, av1, bv[NB4];
    const int KT = K / BK;

    auto ldA = [&](int k0, int row, int kq) -> float4 {
        int m = m0 + row;
        float4 v = make_float4(0.f, 0.f, 0.f, 0.f);
        if (m < M) {
            v = *(const float4*)&A[(size_t)m * K + k0 + kq];
            if (ACT) {
                int kc = k0 + kq;
                v.x = eluf(v.x + bias[kc]);
                v.y = eluf(v.y + bias[kc + 1]);
                v.z = eluf(v.z + bias[kc + 2]);
                v.w = eluf(v.w + bias[kc + 3]);
            }
        }
        return v;
    };
    auto ldB = [&](int k0) {
        #pragma unroll
        for (int j = 0; j < NB4; j++) {
            int idx = t + j * 256;
            int row = idx / (BN / 4), c4 = idx % (BN / 4);
            bv[j] = *(const float4*)&B[(size_t)(k0 + row) * Nc + n0 + c4 * 4];
        }
    };
    auto stTile = [&](int nb) {
        As[nb][ak0 + 0][ar0] = av0.x; As[nb][ak0 + 1][ar0] = av0.y;
        As[nb][ak0 + 2][ar0] = av0.z; As[nb][ak0 + 3][ar0] = av0.w;
        As[nb][ak1 + 0][ar1] = av1.x; As[nb][ak1 + 1][ar1] = av1.y;
        As[nb][ak1 + 2][ar1] = av1.z; As[nb][ak1 + 3][ar1] = av1.w;
        #pragma unroll
        for (int j = 0; j < NB4; j++) {
            int idx = t + j * 256;
            int row = idx / (BN / 4), c4 = idx % (BN / 4);
            *(float4*)&Bs[nb][row][c4 * 4] = bv[j];
        }
    };

    // prologue
    av0 = ldA(0, ar0, ak0);
    av1 = ldA(0, ar1, ak1);
    ldB(0);
    stTile(0);
    __syncthreads();

    int buf = 0;
    for (int kt = 0; kt < KT; kt++) {
        const bool next = (kt + 1 < KT);
        if (next) {
            int k0 = (kt + 1) * BK;
            av0 = ldA(k0, ar0, ak0);
            av1 = ldA(k0, ar1, ak1);
            ldB(k0);
        }
        #pragma unroll
        for (int k = 0; k < BK; k++) {
            float a[TM], b[TN];
            #pragma unroll
            for (int ii = 0; ii < TM; ii++) a[ii] = As[buf][k][tr * TM + ii];
            #pragma unroll
            for (int jj = 0; jj < TN; jj++) b[jj] = Bs[buf][k][tc * TN + jj];
            #pragma unroll
            for (int ii = 0; ii < TM; ii++)
                #pragma unroll
                for (int jj = 0; jj < TN; jj++)
                    acc[ii][jj] = fmaf(a[ii], b[jj], acc[ii][jj]);
        }
        if (next) stTile(buf ^ 1);
        __syncthreads();
        buf ^= 1;
    }

    #pragma unroll
    for (int ii = 0; ii < TM; ii++) {
        int m = m0 + tr * TM + ii;
        if (m < M) {
            #pragma unroll
            for (int jq = 0; jq < TN / 4; jq++) {
                float4 o = make_float4(acc[ii][jq * 4], acc[ii][jq * 4 + 1],
                                       acc[ii][jq * 4 + 2], acc[ii][jq * 4 + 3]);
                *(float4*)&C[(size_t)m * Nc + n0 + tc * TN + jq * 4] = o;
            }
        }
    }
}

__global__ void __launch_bounds__(256) k_gemm1(const float* __restrict__ x,
                                               const float* __restrict__ W1) {
    gemm_body<128, 8, false>(x, W1, g_h1, NN, F1, INDIM, nullptr);
}
// A = elu(g_out1 + b1) fused on load
__global__ void __launch_bounds__(256) k_gemm2(const float* __restrict__ W2,
                                               const float* __restrict__ b1) {
    gemm_body<64, 4, true>(g_out1, W2, g_g2, NN, HIDC, F1, b1);
}

// ---------------- attention coefficients ------------------------------------
// layer 1: warp per node, 4 heads x 64 channels
__global__ void k_attn1(const float* __restrict__ a_src, const float* __restrict__ a_dst) {
    __shared__ float sa[F1], sd[F1];
    int t = threadIdx.x;                 // 256 threads
    sa[t] = a_src[t]; sd[t] = a_dst[t];
    __syncthreads();
    int w = t >> 5, l = t & 31;
    int n = blockIdx.x * 8 + w;
    if (n >= NN) return;
    const float4* hp = (const float4*)(g_h1 + (size_t)n * F1);
    float ss = 0.f, ds = 0.f;
    #pragma unroll
    for (int q = 0; q < 2; q++) {
        float4 v = hp[l * 2 + q];
        int b = l * 8 + q * 4;
        ss += v.x * sa[b] + v.y * sa[b + 1] + v.z * sa[b + 2] + v.w * sa[b + 3];
        ds += v.x * sd[b] + v.y * sd[b + 1] + v.z * sd[b + 2] + v.w * sd[b + 3];
    }
    #pragma unroll
    for (int o = 4; o >= 1; o >>= 1) {
        ss += __shfl_xor_sync(0xFFFFFFFFu, ss, o);
        ds += __shfl_xor_sync(0xFFFFFFFFu, ds, o);
    }
    if ((l & 7) == 0) {
        int h = l >> 3;
        g_as1[n * H1N + h] = ss;
        g_ad1[n * H1N + h] = ds;
    }
}

// layer 2: warp per node, 1 head x 64 channels
__global__ void k_attn2(const float* __restrict__ a_src, const float* __restrict__ a_dst) {
    __shared__ float sa[HIDC], sd[HIDC];
    int t = threadIdx.x;                 // 256 threads
    if (t < HIDC) { sa[t] = a_src[t]; sd[t] = a_dst[t]; }
    __syncthreads();
    int w = t >> 5, l = t & 31;
    int n = blockIdx.x * 8 + w;
    if (n >= NN) return;
    const float2* hp = (const float2*)(g_g2 + (size_t)n * HIDC);
    float2 v = hp[l];
    float ss = v.x * sa[2 * l] + v.y * sa[2 * l + 1];
    float ds = v.x * sd[2 * l] + v.y * sd[2 * l + 1];
    #pragma unroll
    for (int o = 16; o >= 1; o >>= 1) {
        ss += __shfl_xor_sync(0xFFFFFFFFu, ss, o);
        ds += __shfl_xor_sync(0xFFFFFFFFu, ds, o);
    }
    if (l == 0) { g_as2[n] = ss; g_ad2[n] = ds; }
}

// ---------------- fused edge softmax (no max-shift; logits are O(1)) ---------
__global__ void k_edgeAB1() {
    int i = blockIdx.x * blockDim.x + threadIdx.x;
    if (i >= ET) return;
    int s = g_src[i], d = g_dst[i];
    float4 a = *(const float4*)&g_as1[s * H1N];
    float4 b = *(const float4*)&g_ad1[d * H1N];
    float4 ex;
    ex.x = __expf(lrelu02(a.x + b.x));
    ex.y = __expf(lrelu02(a.y + b.y));
    ex.z = __expf(lrelu02(a.z + b.z));
    ex.w = __expf(lrelu02(a.w + b.w));
    *(float4*)&g_e1[i * H1N] = ex;
    redAdd4(&g_s1[d * H1N], ex.x, ex.y, ex.z, ex.w);
}

// aggregation: 16 threads per edge, each owns one float4 column (64 floats/head)
__global__ void k_edgeC1() {
    int t = threadIdx.x;                  // 256
    int c4 = t & 15;
    int i = blockIdx.x * 16 + (t >> 4);
    int s = g_src[i], d = g_dst[i];
    float4 ex = *(const float4*)&g_e1[i * H1N];
    float4 sv = *(const float4*)&g_s1[d * H1N];
    float a0 = ex.x / (sv.x + 1e-16f);
    float a1 = ex.y / (sv.y + 1e-16f);
    float a2 = ex.z / (sv.z + 1e-16f);
    float a3 = ex.w / (sv.w + 1e-16f);
    const float4* hs = (const float4*)(g_h1 + (size_t)s * F1);
    float4* od = (float4*)(g_out1 + (size_t)d * F1);
    float4 v;
    v = hs[c4];      redAdd4((float*)&od[c4],      v.x * a0, v.y * a0, v.z * a0, v.w * a0);
    v = hs[16 + c4]; redAdd4((float*)&od[16 + c4], v.x * a1, v.y * a1, v.z * a1, v.w * a1);
    v = hs[32 + c4]; redAdd4((float*)&od[32 + c4], v.x * a2, v.y * a2, v.z * a2, v.w * a2);
    v = hs[48 + c4]; redAdd4((float*)&od[48 + c4], v.x * a3, v.y * a3, v.z * a3, v.w * a3);
}

__global__ void k_edgeAB2() {
    int i = blockIdx.x * blockDim.x + threadIdx.x;
    if (i >= ET) return;
    int s = g_src[i], d = g_dst[i];
    float ex = __expf(lrelu02(g_as2[s] + g_ad2[d]));
    g_e2[i] = ex;
    atomicAdd(&g_s2[d], ex);
}

__global__ void k_edgeC2() {
    int t = threadIdx.x;                  // 256
    int c4 = t & 15;
    int i = blockIdx.x * 16 + (t >> 4);
    int s = g_src[i], d = g_dst[i];
    float alpha = g_e2[i] / (g_s2[d] + 1e-16f);
    float4 v = ((const float4*)(g_g2 + (size_t)s * HIDC))[c4];
    redAdd4(g_out2 + (size_t)d * HIDC + c4 * 4,
            v.x * alpha, v.y * alpha, v.z * alpha, v.w * alpha);
}

// ---------------- classifier MLP: relu(elu(z+b2)@W3+b3)@W4+b4 ---------------
__global__ void k_mlp(const float* __restrict__ b2,
                      const float* __restrict__ W3, const float* __restrict__ b3,
                      const float* __restrict__ W4, const float* __restrict__ b4,
                      float* __restrict__ out) {
    __shared__ float sW3[64 * 32];
    __shared__ float sb3[32];
    __shared__ float sW4[32 * 2];
    __shared__ float sb4[2];
    __shared__ float sb2[64];
    __shared__ float sz[32][65];
    __shared__ float sh[32][33];
    int t = threadIdx.x;                  // 128 threads, 32 nodes per block
    for (int j = t; j < 2048; j += 128) sW3[j] = W3[j];
    if (t < 32) sb3[t] = b3[t];
    if (t < 64) { sW4[t] = W4[t]; sb2[t] = b2[t]; }
    if (t < 2)  sb4[t] = b4[t];
    __syncthreads();
    int n0 = blockIdx.x * 32;
    for (int j = t; j < 2048; j += 128) {
        int r = j >> 6, c = j & 63;
        int n = n0 + r;
        sz[r][c] = (n < NN) ? eluf(g_out2[(size_t)n * HIDC + c] + sb2[c]) : 0.f;
    }
    __syncthreads();
    for (int j = t; j < 1024; j += 128) {
        int r = j >> 5, hh = j & 31;
        float acc = sb3[hh];
        #pragma unroll
        for (int k = 0; k < 64; k++) acc += sz[r][k] * sW3[k * 32 + hh];
        sh[r][hh] = fmaxf(acc, 0.f);
    }
    __syncthreads();
    if (t < 64) {
        int r = t >> 1, o = t & 1;
        int n = n0 + r;
        if (n < NN) {
            float acc = sb4[o];
            #pragma unroll
            for (int k = 0; k < 32; k++) acc += sh[r][k] * sW4[k * 2 + o];
            out[(size_t)n * 2 + o] = acc;
        }
    }
}

// ---------------- launch -----------------------------------------------------
extern "C" void kernel_launch(void* const* d_in, const int* in_sizes, int n_in,
                              void* d_out, int out_size) {
    const float* x       = (const float*)d_in[0];
    const void*  eidx    = d_in[1];
    const float* W1      = (const float*)d_in[2];
    const float* a_src1  = (const float*)d_in[3];
    const float* a_dst1  = (const float*)d_in[4];
    const float* b1      = (const float*)d_in[5];
    const float* W2      = (const float*)d_in[6];
    const float* a_src2  = (const float*)d_in[7];
    const float* a_dst2  = (const float*)d_in[8];
    const float* b2      = (const float*)d_in[9];
    const float* W3      = (const float*)d_in[10];
    const float* b3      = (const float*)d_in[11];
    const float* W4      = (const float*)d_in[12];
    const float* b4      = (const float*)d_in[13];
    float* out = (float*)d_out;

    k_init<<<2048, 256>>>();
    k_detect<<<(EE + 255) / 256, 256>>>((const unsigned int*)eidx);
    k_convert<<<(ET + 255) / 256, 256>>>((const int*)eidx);

    // layer 1
    k_gemm1<<<dim3(F1 / 128, (NN + 127) / 128), 256>>>(x, W1);
    k_attn1<<<(NN + 7) / 8, 256>>>(a_src1, a_dst1);
    k_edgeAB1<<<(ET + 255) / 256, 256>>>();
    k_edgeC1<<<(ET + 15) / 16, 256>>>();

    // layer 2 (bias+ELU of layer1 fused into gemm2's A load)
    k_gemm2<<<dim3(HIDC / 64, (NN + 127) / 128), 256>>>(W2, b1);
    k_attn2<<<(NN + 7) / 8, 256>>>(a_src2, a_dst2);
    k_edgeAB2<<<(ET + 255) / 256, 256>>>();
    k_edgeC2<<<(ET + 15) / 16, 256>>>();

    // classifier (bias+ELU of layer2 fused into MLP input load)
    k_mlp<<<(NN + 31) / 32, 128>>>(b2, W3, b3, W4, b4, out);
}

// round 9
// speedup vs baseline: 1.6402x; 1.1712x over previous
#include <cuda_runtime.h>

#define NN    50000
#define EE    800000
#define ET    (EE + NN)        // edges + self loops = 850000
#define INDIM 128
#define HIDC  64
#define H1N   4
#define F1    256              // 4 heads * 64

// ---------------- scratch (device globals; no allocation allowed) ----------
__device__ __align__(16) float g_h1  [NN * F1];    // x @ W1
__device__ __align__(16) float g_out1[NN * F1];    // layer1 aggregated (normalized)
__device__ __align__(16) float g_as1 [NN * H1N];
__device__ __align__(16) float g_ad1 [NN * H1N];
__device__ __align__(16) float g_g2  [NN * HIDC];  // elu(out1+b1) @ W2
__device__ __align__(16) float g_out2[NN * HIDC];  // layer2 aggregated (normalized)
__device__ __align__(16) float g_as2 [NN];
__device__ __align__(16) float g_ad2 [NN];
__device__ int g_rowptr[NN + 1];
__device__ int g_fill[NN];
__device__ int g_csrc[ET];
__device__ int g_is64;

// ---------------- helpers ---------------------------------------------------
__device__ __forceinline__ float lrelu02(float x) { return x > 0.f ? x : 0.2f * x; }
__device__ __forceinline__ float eluf(float x)    { return x > 0.f ? x : (__expf(x) - 1.f); }

// ---------------- CSR build -------------------------------------------------
__global__ void k_init0() {
    int i = blockIdx.x * blockDim.x + threadIdx.x;
    if (i == 0) g_is64 = 1;
    if (i < NN) g_fill[i] = 0;
}

// int64-vs-int32 edge_index detection: if int64, high words of first E entries are 0
__global__ void k_detect(const unsigned int* __restrict__ w) {
    int i = blockIdx.x * blockDim.x + threadIdx.x;
    if (i < EE) {
        if (w[2 * i + 1] != 0u) g_is64 = 0;
    }
}

__global__ void k_hist(const int* __restrict__ w) {
    int i = blockIdx.x * blockDim.x + threadIdx.x;
    if (i >= ET) return;
    int d;
    if (i < EE) d = g_is64 ? w[2 * EE + 2 * i] : w[EE + i];
    else        d = i - EE;
    atomicAdd(&g_fill[d], 1);
}

// single-block exclusive scan over g_fill -> g_rowptr, and reset g_fill to offsets
__global__ void k_scan() {
    __shared__ int partial[1024];
    const int t = threadIdx.x;
    const int CH = (NN + 1023) / 1024;     // 49
    const int base = t * CH;
    int s = 0;
    for (int j = 0; j < CH; j++) {
        int idx = base + j;
        if (idx < NN) s += g_fill[idx];
    }
    partial[t] = s;
    __syncthreads();
    for (int off = 1; off < 1024; off <<= 1) {
        int v = (t >= off) ? partial[t - off] : 0;
        __syncthreads();
        partial[t] += v;
        __syncthreads();
    }
    int run = partial[t] - s;              // exclusive prefix at chunk start
    for (int j = 0; j < CH; j++) {
        int idx = base + j;
        if (idx < NN) {
            int c = g_fill[idx];
            g_rowptr[idx] = run;
            g_fill[idx]   = run;
            run += c;
        }
    }
    if (t == 1023) g_rowptr[NN] = ET;
}

__global__ void k_place(const int* __restrict__ w) {
    int i = blockIdx.x * blockDim.x + threadIdx.x;
    if (i >= ET) return;
    int s, d;
    if (i < EE) {
        if (g_is64) { s = w[2 * i]; d = w[2 * EE + 2 * i]; }
        else        { s = w[i];     d = w[EE + i]; }
    } else {
        s = d = i - EE;
    }
    int pos = atomicAdd(&g_fill[d], 1);
    g_csrc[pos] = s;
}

// ---------------- double-buffered register-tiled fp32 GEMM -------------------
// BM=128, BK=16, TM=8, 256 threads. BN/TN templated (128/8 or 64/4).
// ACT: apply elu(a + bias[kcol]) to A elements on load.
template <int BN, int TN, bool ACT>
__device__ __forceinline__ void gemm_body(const float* __restrict__ A,
                                          const float* __restrict__ B,
                                          float* __restrict__ C,
                                          int M, int Nc, int K,
                                          const float* __restrict__ bias) {
    constexpr int BM = 128, BK = 16, TM = 8;
    constexpr int NB4 = (BK * BN / 4) / 256;   // B float4 loads per thread (2 or 1)
    __shared__ float As[2][BK][BM + 4];
    __shared__ float Bs[2][BK][BN];
    const int t  = threadIdx.x;
    const int tr = t >> 4;            // 0..15
    const int tc = t & 15;            // 0..15
    const int m0 = blockIdx.y * BM, n0 = blockIdx.x * BN;

    const int ar0 = (2 * t) / 4,     ak0 = ((2 * t)     & 3) * 4;
    const int ar1 = (2 * t + 1) / 4, ak1 = ((2 * t + 1) & 3) * 4;

    float acc[TM][TN] = {};
    float4 av0, av1, bv[NB4];
    const int KT = K / BK;

    auto ldA = [&](int k0, int row, int kq) -> float4 {
        int m = m0 + row;
        float4 v = make_float4(0.f, 0.f, 0.f, 0.f);
        if (m < M) {
            v = *(const float4*)&A[(size_t)m * K + k0 + kq];
            if (ACT) {
                int kc = k0 + kq;
                v.x = eluf(v.x + bias[kc]);
                v.y = eluf(v.y + bias[kc + 1]);
                v.z = eluf(v.z + bias[kc + 2]);
                v.w = eluf(v.w + bias[kc + 3]);
            }
        }
        return v;
    };
    auto ldB = [&](int k0) {
        #pragma unroll
        for (int j = 0; j < NB4; j++) {
            int idx = t + j * 256;
            int row = idx / (BN / 4), c4 = idx % (BN / 4);
            bv[j] = *(const float4*)&B[(size_t)(k0 + row) * Nc + n0 + c4 * 4];
        }
    };
    auto stTile = [&](int nb) {
        As[nb][ak0 + 0][ar0] = av0.x; As[nb][ak0 + 1][ar0] = av0.y;
        As[nb][ak0 + 2][ar0] = av0.z; As[nb][ak0 + 3][ar0] = av0.w;
        As[nb][ak1 + 0][ar1] = av1.x; As[nb][ak1 + 1][ar1] = av1.y;
        As[nb][ak1 + 2][ar1] = av1.z; As[nb][ak1 + 3][ar1] = av1.w;
        #pragma unroll
        for (int j = 0; j < NB4; j++) {
            int idx = t + j * 256;
            int row = idx / (BN / 4), c4 = idx % (BN / 4);
            *(float4*)&Bs[nb][row][c4 * 4] = bv[j];
        }
    };

    av0 = ldA(0, ar0, ak0);
    av1 = ldA(0, ar1, ak1);
    ldB(0);
    stTile(0);
    __syncthreads();

    int buf = 0;
    for (int kt = 0; kt < KT; kt++) {
        const bool next = (kt + 1 < KT);
        if (next) {
            int k0 = (kt + 1) * BK;
            av0 = ldA(k0, ar0, ak0);
            av1 = ldA(k0, ar1, ak1);
            ldB(k0);
        }
        #pragma unroll
        for (int k = 0; k < BK; k++) {
            float a[TM], b[TN];
            #pragma unroll
            for (int iq = 0; iq < TM / 4; iq++) {
                float4 a4 = *(const float4*)&As[buf][k][tr * TM + iq * 4];
                a[iq * 4] = a4.x; a[iq * 4 + 1] = a4.y; a[iq * 4 + 2] = a4.z; a[iq * 4 + 3] = a4.w;
            }
            #pragma unroll
            for (int jq = 0; jq < TN / 4; jq++) {
                float4 b4 = *(const float4*)&Bs[buf][k][tc * TN + jq * 4];
                b[jq * 4] = b4.x; b[jq * 4 + 1] = b4.y; b[jq * 4 + 2] = b4.z; b[jq * 4 + 3] = b4.w;
            }
            #pragma unroll
            for (int ii = 0; ii < TM; ii++)
                #pragma unroll
                for (int jj = 0; jj < TN; jj++)
                    acc[ii][jj] = fmaf(a[ii], b[jj], acc[ii][jj]);
        }
        if (next) stTile(buf ^ 1);
        __syncthreads();
        buf ^= 1;
    }

    #pragma unroll
    for (int ii = 0; ii < TM; ii++) {
        int m = m0 + tr * TM + ii;
        if (m < M) {
            #pragma unroll
            for (int jq = 0; jq < TN / 4; jq++) {
                float4 o = make_float4(acc[ii][jq * 4], acc[ii][jq * 4 + 1],
                                       acc[ii][jq * 4 + 2], acc[ii][jq * 4 + 3]);
                *(float4*)&C[(size_t)m * Nc + n0 + tc * TN + jq * 4] = o;
            }
        }
    }
}

__global__ void __launch_bounds__(256) k_gemm1(const float* __restrict__ x,
                                               const float* __restrict__ W1) {
    gemm_body<128, 8, false>(x, W1, g_h1, NN, F1, INDIM, nullptr);
}
// A = elu(g_out1 + b1) fused on load
__global__ void __launch_bounds__(256) k_gemm2(const float* __restrict__ W2,
                                               const float* __restrict__ b1) {
    gemm_body<64, 4, true>(g_out1, W2, g_g2, NN, HIDC, F1, b1);
}

// ---------------- attention coefficients ------------------------------------
// layer 1: warp per node, 4 heads x 64 channels
__global__ void k_attn1(const float* __restrict__ a_src, const float* __restrict__ a_dst) {
    __shared__ float sa[F1], sd[F1];
    int t = threadIdx.x;                 // 256 threads
    sa[t] = a_src[t]; sd[t] = a_dst[t];
    __syncthreads();
    int w = t >> 5, l = t & 31;
    int n = blockIdx.x * 8 + w;
    if (n >= NN) return;
    const float4* hp = (const float4*)(g_h1 + (size_t)n * F1);
    float ss = 0.f, ds = 0.f;
    #pragma unroll
    for (int q = 0; q < 2; q++) {
        float4 v = hp[l * 2 + q];
        int b = l * 8 + q * 4;
        ss += v.x * sa[b] + v.y * sa[b + 1] + v.z * sa[b + 2] + v.w * sa[b + 3];
        ds += v.x * sd[b] + v.y * sd[b + 1] + v.z * sd[b + 2] + v.w * sd[b + 3];
    }
    #pragma unroll
    for (int o = 4; o >= 1; o >>= 1) {
        ss += __shfl_xor_sync(0xFFFFFFFFu, ss, o);
        ds += __shfl_xor_sync(0xFFFFFFFFu, ds, o);
    }
    if ((l & 7) == 0) {
        int h = l >> 3;
        g_as1[n * H1N + h] = ss;
        g_ad1[n * H1N + h] = ds;
    }
}

// layer 2: warp per node, 1 head x 64 channels
__global__ void k_attn2(const float* __restrict__ a_src, const float* __restrict__ a_dst) {
    __shared__ float sa[HIDC], sd[HIDC];
    int t = threadIdx.x;                 // 256 threads
    if (t < HIDC) { sa[t] = a_src[t]; sd[t] = a_dst[t]; }
    __syncthreads();
    int w = t >> 5, l = t & 31;
    int n = blockIdx.x * 8 + w;
    if (n >= NN) return;
    const float2* hp = (const float2*)(g_g2 + (size_t)n * HIDC);
    float2 v = hp[l];
    float ss = v.x * sa[2 * l] + v.y * sa[2 * l + 1];
    float ds = v.x * sd[2 * l] + v.y * sd[2 * l + 1];
    #pragma unroll
    for (int o = 16; o >= 1; o >>= 1) {
        ss += __shfl_xor_sync(0xFFFFFFFFu, ss, o);
        ds += __shfl_xor_sync(0xFFFFFFFFu, ds, o);
    }
    if (l == 0) { g_as2[n] = ss; g_ad2[n] = ds; }
}

// ---------------- fused CSR gather aggregation, layer 1 ----------------------
// warp per destination node. Softmax normalization factored out:
// out[d] = sum_e ex_e * h[src_e] / sum_e ex_e  (per head).
// lane L owns float4 columns L (head L>>4 in {0,1}) and L+32 (head 2+(L>>4)).
__global__ void __launch_bounds__(256) k_agg1() {
    int wid = (blockIdx.x * blockDim.x + threadIdx.x) >> 5;
    int l = threadIdx.x & 31;
    if (wid >= NN) return;
    const int d = wid;
    const int r0 = g_rowptr[d], r1 = g_rowptr[d + 1];
    float4 ad4 = *(const float4*)&g_ad1[d * H1N];
    const bool lo = (l < 16);
    const float ad_a = lo ? ad4.x : ad4.y;
    const float ad_b = lo ? ad4.z : ad4.w;
    float4 acc0 = make_float4(0.f, 0.f, 0.f, 0.f);
    float4 acc1 = make_float4(0.f, 0.f, 0.f, 0.f);
    float sum0 = 0.f, sum1 = 0.f;
    for (int e = r0; e < r1; e++) {
        int s = g_csrc[e];
        float4 as4 = *(const float4*)&g_as1[s * H1N];
        float e0 = __expf(lrelu02((lo ? as4.x : as4.y) + ad_a));
        float e1 = __expf(lrelu02((lo ? as4.z : as4.w) + ad_b));
        sum0 += e0; sum1 += e1;
        const float4* hp = (const float4*)(g_h1 + (size_t)s * F1);
        float4 v0 = hp[l], v1 = hp[l + 32];
        acc0.x = fmaf(e0, v0.x, acc0.x); acc0.y = fmaf(e0, v0.y, acc0.y);
        acc0.z = fmaf(e0, v0.z, acc0.z); acc0.w = fmaf(e0, v0.w, acc0.w);
        acc1.x = fmaf(e1, v1.x, acc1.x); acc1.y = fmaf(e1, v1.y, acc1.y);
        acc1.z = fmaf(e1, v1.z, acc1.z); acc1.w = fmaf(e1, v1.w, acc1.w);
    }
    float inv0 = 1.f / (sum0 + 1e-16f);
    float inv1 = 1.f / (sum1 + 1e-16f);
    float4* op = (float4*)(g_out1 + (size_t)d * F1);
    op[l]      = make_float4(acc0.x * inv0, acc0.y * inv0, acc0.z * inv0, acc0.w * inv0);
    op[l + 32] = make_float4(acc1.x * inv1, acc1.y * inv1, acc1.z * inv1, acc1.w * inv1);
}

// ---------------- fused CSR gather aggregation, layer 2 ----------------------
// warp per destination node, lane owns 2 channels.
__global__ void __launch_bounds__(256) k_agg2() {
    int wid = (blockIdx.x * blockDim.x + threadIdx.x) >> 5;
    int l = threadIdx.x & 31;
    if (wid >= NN) return;
    const int d = wid;
    const int r0 = g_rowptr[d], r1 = g_rowptr[d + 1];
    const float ad = g_ad2[d];
    float2 acc = make_float2(0.f, 0.f);
    float sum = 0.f;
    for (int e = r0; e < r1; e++) {
        int s = g_csrc[e];
        float ex = __expf(lrelu02(g_as2[s] + ad));
        sum += ex;
        float2 v = ((const float2*)(g_g2 + (size_t)s * HIDC))[l];
        acc.x = fmaf(ex, v.x, acc.x);
        acc.y = fmaf(ex, v.y, acc.y);
    }
    float inv = 1.f / (sum + 1e-16f);
    ((float2*)(g_out2 + (size_t)d * HIDC))[l] = make_float2(acc.x * inv, acc.y * inv);
}

// ---------------- classifier MLP: relu(elu(z+b2)@W3+b3)@W4+b4 ---------------
__global__ void k_mlp(const float* __restrict__ b2,
                      const float* __restrict__ W3, const float* __restrict__ b3,
                      const float* __restrict__ W4, const float* __restrict__ b4,
                      float* __restrict__ out) {
    __shared__ float sW3[64 * 32];
    __shared__ float sb3[32];
    __shared__ float sW4[32 * 2];
    __shared__ float sb4[2];
    __shared__ float sb2[64];
    __shared__ float sz[32][65];
    __shared__ float sh[32][33];
    int t = threadIdx.x;                  // 128 threads, 32 nodes per block
    for (int j = t; j < 2048; j += 128) sW3[j] = W3[j];
    if (t < 32) sb3[t] = b3[t];
    if (t < 64) { sW4[t] = W4[t]; sb2[t] = b2[t]; }
    if (t < 2)  sb4[t] = b4[t];
    __syncthreads();
    int n0 = blockIdx.x * 32;
    for (int j = t; j < 2048; j += 128) {
        int r = j >> 6, c = j & 63;
        int n = n0 + r;
        sz[r][c] = (n < NN) ? eluf(g_out2[(size_t)n * HIDC + c] + sb2[c]) : 0.f;
    }
    __syncthreads();
    for (int j = t; j < 1024; j += 128) {
        int r = j >> 5, hh = j & 31;
        float acc = sb3[hh];
        #pragma unroll
        for (int k = 0; k < 64; k++) acc += sz[r][k] * sW3[k * 32 + hh];
        sh[r][hh] = fmaxf(acc, 0.f);
    }
    __syncthreads();
    if (t < 64) {
        int r = t >> 1, o = t & 1;
        int n = n0 + r;
        if (n < NN) {
            float acc = sb4[o];
            #pragma unroll
            for (int k = 0; k < 32; k++) acc += sh[r][k] * sW4[k * 2 + o];
            out[(size_t)n * 2 + o] = acc;
        }
    }
}

// ---------------- launch -----------------------------------------------------
extern "C" void kernel_launch(void* const* d_in, const int* in_sizes, int n_in,
                              void* d_out, int out_size) {
    const float* x       = (const float*)d_in[0];
    const void*  eidx    = d_in[1];
    const float* W1      = (const float*)d_in[2];
    const float* a_src1  = (const float*)d_in[3];
    const float* a_dst1  = (const float*)d_in[4];
    const float* b1      = (const float*)d_in[5];
    const float* W2      = (const float*)d_in[6];
    const float* a_src2  = (const float*)d_in[7];
    const float* a_dst2  = (const float*)d_in[8];
    const float* b2      = (const float*)d_in[9];
    const float* W3      = (const float*)d_in[10];
    const float* b3      = (const float*)d_in[11];
    const float* W4      = (const float*)d_in[12];
    const float* b4      = (const float*)d_in[13];
    float* out = (float*)d_out;

    // CSR build
    k_init0<<<(NN + 255) / 256, 256>>>();
    k_detect<<<(EE + 255) / 256, 256>>>((const unsigned int*)eidx);
    k_hist<<<(ET + 255) / 256, 256>>>((const int*)eidx);
    k_scan<<<1, 1024>>>();
    k_place<<<(ET + 255) / 256, 256>>>((const int*)eidx);

    // layer 1
    k_gemm1<<<dim3(F1 / 128, (NN + 127) / 128), 256>>>(x, W1);
    k_attn1<<<(NN + 7) / 8, 256>>>(a_src1, a_dst1);
    k_agg1<<<(NN * 32 + 255) / 256, 256>>>();

    // layer 2 (bias+ELU of layer1 fused into gemm2's A load)
    k_gemm2<<<dim3(HIDC / 64, (NN + 127) / 128), 256>>>(W2, b1);
    k_attn2<<<(NN + 7) / 8, 256>>>(a_src2, a_dst2);
    k_agg2<<<(NN * 32 + 255) / 256, 256>>>();

    // classifier (bias+ELU of layer2 fused into MLP input load)
    k_mlp<<<(NN + 31) / 32, 128>>>(b2, W3, b3, W4, b4, out);
}

// round 10
// speedup vs baseline: 1.9409x; 1.1834x over previous
#include <cuda_runtime.h>

#define NN    50000
#define EE    800000
#define ET    (EE + NN)        // edges + self loops = 850000
#define INDIM 128
#define HIDC  64
#define H1N   4
#define F1    256              // 4 heads * 64

#define SCB   256              // scan chunk (nodes per block)
#define NB    ((NN + SCB - 1) / SCB)   // 196 scan blocks

// ---------------- scratch (device globals; no allocation allowed) ----------
__device__ __align__(16) float g_h1  [NN * F1];    // x @ W1
__device__ __align__(16) float g_out1[NN * F1];    // layer1 aggregated (normalized)
__device__ __align__(16) float g_as1 [NN * H1N];
__device__ __align__(16) float g_ad1 [NN * H1N];
__device__ __align__(16) float g_g2  [NN * HIDC];  // elu(out1+b1) @ W2
__device__ __align__(16) float g_out2[NN * HIDC];  // layer2 aggregated (normalized)
__device__ __align__(16) float g_as2 [NN];
__device__ __align__(16) float g_ad2 [NN];
__device__ int g_rowptr[NN + 1];
__device__ int g_fill[NN];
__device__ int g_bsum[NB];
__device__ int g_csrc[ET];
__device__ int g_is64;

// ---------------- helpers ---------------------------------------------------
__device__ __forceinline__ float lrelu02(float x) { return x > 0.f ? x : 0.2f * x; }
__device__ __forceinline__ float eluf(float x)    { return x > 0.f ? x : (__expf(x) - 1.f); }

// ---------------- CSR build -------------------------------------------------
__global__ void k_init0() {
    int i = blockIdx.x * blockDim.x + threadIdx.x;
    if (i == 0) g_is64 = 1;
    if (i < NN) g_fill[i] = 0;
}

// int64-vs-int32 edge_index detection: if int64, high words of first E entries are 0
__global__ void k_detect(const unsigned int* __restrict__ w) {
    int i = blockIdx.x * blockDim.x + threadIdx.x;
    if (i < EE) {
        if (w[2 * i + 1] != 0u) g_is64 = 0;
    }
}

__global__ void k_hist(const int* __restrict__ w) {
    int i = blockIdx.x * blockDim.x + threadIdx.x;
    if (i >= ET) return;
    int d;
    if (i < EE) d = g_is64 ? w[2 * EE + 2 * i] : w[EE + i];
    else        d = i - EE;
    atomicAdd(&g_fill[d], 1);
}

// ---- multi-block exclusive scan of g_fill -> g_rowptr -----------------------
// phase A: per-block scan of a 256-node chunk; local exclusive prefix to
// g_rowptr, chunk total to g_bsum.
__global__ void k_scanA() {
    __shared__ int wsum[8];
    const int t = threadIdx.x;            // 256
    const int i = blockIdx.x * SCB + t;
    const int l = t & 31, w = t >> 5;
    int v = (i < NN) ? g_fill[i] : 0;
    // inclusive warp scan
    int x = v;
    #pragma unroll
    for (int o = 1; o < 32; o <<= 1) {
        int y = __shfl_up_sync(0xFFFFFFFFu, x, o);
        if (l >= o) x += y;
    }
    if (l == 31) wsum[w] = x;
    __syncthreads();
    if (w == 0) {
        int s = (l < 8) ? wsum[l] : 0;
        #pragma unroll
        for (int o = 1; o < 8; o <<= 1) {
            int y = __shfl_up_sync(0xFFFFFFFFu, s, o);
            if (l >= o) s += y;
        }
        if (l < 8) wsum[l] = s;
    }
    __syncthreads();
    int excl = x - v + (w > 0 ? wsum[w - 1] : 0);
    if (i < NN) g_rowptr[i] = excl;
    if (t == 255) g_bsum[blockIdx.x] = excl + v;
}

// phase B: single block exclusive scan of NB block totals (NB <= 256)
__global__ void k_scanB() {
    __shared__ int wsum[8];
    const int t = threadIdx.x;            // 256
    const int l = t & 31, w = t >> 5;
    int v = (t < NB) ? g_bsum[t] : 0;
    int x = v;
    #pragma unroll
    for (int o = 1; o < 32; o <<= 1) {
        int y = __shfl_up_sync(0xFFFFFFFFu, x, o);
        if (l >= o) x += y;
    }
    if (l == 31) wsum[w] = x;
    __syncthreads();
    if (w == 0) {
        int s = (l < 8) ? wsum[l] : 0;
        #pragma unroll
        for (int o = 1; o < 8; o <<= 1) {
            int y = __shfl_up_sync(0xFFFFFFFFu, s, o);
            if (l >= o) s += y;
        }
        if (l < 8) wsum[l] = s;
    }
    __syncthreads();
    int excl = x - v + (w > 0 ? wsum[w - 1] : 0);
    if (t < NB) g_bsum[t] = excl;
}

// phase C: add block offsets; mirror into g_fill; close rowptr
__global__ void k_scanC() {
    const int i = blockIdx.x * SCB + threadIdx.x;
    if (i < NN) {
        int r = g_rowptr[i] + g_bsum[blockIdx.x];
        g_rowptr[i] = r;
        g_fill[i]   = r;
    }
    if (i == 0) g_rowptr[NN] = ET;
}

__global__ void k_place(const int* __restrict__ w) {
    int i = blockIdx.x * blockDim.x + threadIdx.x;
    if (i >= ET) return;
    int s, d;
    if (i < EE) {
        if (g_is64) { s = w[2 * i]; d = w[2 * EE + 2 * i]; }
        else        { s = w[i];     d = w[EE + i]; }
    } else {
        s = d = i - EE;
    }
    int pos = atomicAdd(&g_fill[d], 1);
    g_csrc[pos] = s;
}

// ---------------- double-buffered register-tiled fp32 GEMM -------------------
// BM=128, BK=16, TM=8, 256 threads. BN/TN templated (128/8 or 64/4).
// ACT: apply elu(a + bias[kcol]) to A elements on load.
template <int BN, int TN, bool ACT>
__device__ __forceinline__ void gemm_body(const float* __restrict__ A,
                                          const float* __restrict__ B,
                                          float* __restrict__ C,
                                          int M, int Nc, int K,
                                          const float* __restrict__ bias) {
    constexpr int BM = 128, BK = 16, TM = 8;
    constexpr int NB4 = (BK * BN / 4) / 256;   // B float4 loads per thread (2 or 1)
    __shared__ float As[2][BK][BM + 4];
    __shared__ float Bs[2][BK][BN];
    const int t  = threadIdx.x;
    const int tr = t >> 4;            // 0..15
    const int tc = t & 15;            // 0..15
    const int m0 = blockIdx.y * BM, n0 = blockIdx.x * BN;

    const int ar0 = (2 * t) / 4,     ak0 = ((2 * t)     & 3) * 4;
    const int ar1 = (2 * t + 1) / 4, ak1 = ((2 * t + 1) & 3) * 4;

    float acc[TM][TN] = {};
    float4 av0, av1, bv[NB4];
    const int KT = K / BK;

    auto ldA = [&](int k0, int row, int kq) -> float4 {
        int m = m0 + row;
        float4 v = make_float4(0.f, 0.f, 0.f, 0.f);
        if (m < M) {
            v = *(const float4*)&A[(size_t)m * K + k0 + kq];
            if (ACT) {
                int kc = k0 + kq;
                v.x = eluf(v.x + bias[kc]);
                v.y = eluf(v.y + bias[kc + 1]);
                v.z = eluf(v.z + bias[kc + 2]);
                v.w = eluf(v.w + bias[kc + 3]);
            }
        }
        return v;
    };
    auto ldB = [&](int k0) {
        #pragma unroll
        for (int j = 0; j < NB4; j++) {
            int idx = t + j * 256;
            int row = idx / (BN / 4), c4 = idx % (BN / 4);
            bv[j] = *(const float4*)&B[(size_t)(k0 + row) * Nc + n0 + c4 * 4];
        }
    };
    auto stTile = [&](int nb) {
        As[nb][ak0 + 0][ar0] = av0.x; As[nb][ak0 + 1][ar0] = av0.y;
        As[nb][ak0 + 2][ar0] = av0.z; As[nb][ak0 + 3][ar0] = av0.w;
        As[nb][ak1 + 0][ar1] = av1.x; As[nb][ak1 + 1][ar1] = av1.y;
        As[nb][ak1 + 2][ar1] = av1.z; As[nb][ak1 + 3][ar1] = av1.w;
        #pragma unroll
        for (int j = 0; j < NB4; j++) {
            int idx = t + j * 256;
            int row = idx / (BN / 4), c4 = idx % (BN / 4);
            *(float4*)&Bs[nb][row][c4 * 4] = bv[j];
        }
    };

    av0 = ldA(0, ar0, ak0);
    av1 = ldA(0, ar1, ak1);
    ldB(0);
    stTile(0);
    __syncthreads();

    int buf = 0;
    for (int kt = 0; kt < KT; kt++) {
        const bool next = (kt + 1 < KT);
        if (next) {
            int k0 = (kt + 1) * BK;
            av0 = ldA(k0, ar0, ak0);
            av1 = ldA(k0, ar1, ak1);
            ldB(k0);
        }
        #pragma unroll
        for (int k = 0; k < BK; k++) {
            float a[TM], b[TN];
            #pragma unroll
            for (int iq = 0; iq < TM / 4; iq++) {
                float4 a4 = *(const float4*)&As[buf][k][tr * TM + iq * 4];
                a[iq * 4] = a4.x; a[iq * 4 + 1] = a4.y; a[iq * 4 + 2] = a4.z; a[iq * 4 + 3] = a4.w;
            }
            #pragma unroll
            for (int jq = 0; jq < TN / 4; jq++) {
                float4 b4 = *(const float4*)&Bs[buf][k][tc * TN + jq * 4];
                b[jq * 4] = b4.x; b[jq * 4 + 1] = b4.y; b[jq * 4 + 2] = b4.z; b[jq * 4 + 3] = b4.w;
            }
            #pragma unroll
            for (int ii = 0; ii < TM; ii++)
                #pragma unroll
                for (int jj = 0; jj < TN; jj++)
                    acc[ii][jj] = fmaf(a[ii], b[jj], acc[ii][jj]);
        }
        if (next) stTile(buf ^ 1);
        __syncthreads();
        buf ^= 1;
    }

    #pragma unroll
    for (int ii = 0; ii < TM; ii++) {
        int m = m0 + tr * TM + ii;
        if (m < M) {
            #pragma unroll
            for (int jq = 0; jq < TN / 4; jq++) {
                float4 o = make_float4(acc[ii][jq * 4], acc[ii][jq * 4 + 1],
                                       acc[ii][jq * 4 + 2], acc[ii][jq * 4 + 3]);
                *(float4*)&C[(size_t)m * Nc + n0 + tc * TN + jq * 4] = o;
            }
        }
    }
}

__global__ void __launch_bounds__(256) k_gemm1(const float* __restrict__ x,
                                               const float* __restrict__ W1) {
    gemm_body<128, 8, false>(x, W1, g_h1, NN, F1, INDIM, nullptr);
}
// A = elu(g_out1 + b1) fused on load
__global__ void __launch_bounds__(256) k_gemm2(const float* __restrict__ W2,
                                               const float* __restrict__ b1) {
    gemm_body<64, 4, true>(g_out1, W2, g_g2, NN, HIDC, F1, b1);
}

// ---------------- attention coefficients ------------------------------------
// layer 1: warp per node, 4 heads x 64 channels
__global__ void k_attn1(const float* __restrict__ a_src, const float* __restrict__ a_dst) {
    __shared__ float sa[F1], sd[F1];
    int t = threadIdx.x;                 // 256 threads
    sa[t] = a_src[t]; sd[t] = a_dst[t];
    __syncthreads();
    int w = t >> 5, l = t & 31;
    int n = blockIdx.x * 8 + w;
    if (n >= NN) return;
    const float4* hp = (const float4*)(g_h1 + (size_t)n * F1);
    float ss = 0.f, ds = 0.f;
    #pragma unroll
    for (int q = 0; q < 2; q++) {
        float4 v = hp[l * 2 + q];
        int b = l * 8 + q * 4;
        ss += v.x * sa[b] + v.y * sa[b + 1] + v.z * sa[b + 2] + v.w * sa[b + 3];
        ds += v.x * sd[b] + v.y * sd[b + 1] + v.z * sd[b + 2] + v.w * sd[b + 3];
    }
    #pragma unroll
    for (int o = 4; o >= 1; o >>= 1) {
        ss += __shfl_xor_sync(0xFFFFFFFFu, ss, o);
        ds += __shfl_xor_sync(0xFFFFFFFFu, ds, o);
    }
    if ((l & 7) == 0) {
        int h = l >> 3;
        g_as1[n * H1N + h] = ss;
        g_ad1[n * H1N + h] = ds;
    }
}

// layer 2: warp per node, 1 head x 64 channels
__global__ void k_attn2(const float* __restrict__ a_src, const float* __restrict__ a_dst) {
    __shared__ float sa[HIDC], sd[HIDC];
    int t = threadIdx.x;                 // 256 threads
    if (t < HIDC) { sa[t] = a_src[t]; sd[t] = a_dst[t]; }
    __syncthreads();
    int w = t >> 5, l = t & 31;
    int n = blockIdx.x * 8 + w;
    if (n >= NN) return;
    const float2* hp = (const float2*)(g_g2 + (size_t)n * HIDC);
    float2 v = hp[l];
    float ss = v.x * sa[2 * l] + v.y * sa[2 * l + 1];
    float ds = v.x * sd[2 * l] + v.y * sd[2 * l + 1];
    #pragma unroll
    for (int o = 16; o >= 1; o >>= 1) {
        ss += __shfl_xor_sync(0xFFFFFFFFu, ss, o);
        ds += __shfl_xor_sync(0xFFFFFFFFu, ds, o);
    }
    if (l == 0) { g_as2[n] = ss; g_ad2[n] = ds; }
}

// ---------------- fused CSR gather aggregation, layer 1 ----------------------
// warp per destination node. Softmax normalization factored out:
// out[d] = sum_e ex_e * h[src_e] / sum_e ex_e  (per head).
// lane L owns float4 columns L (head L>>4 in {0,1}) and L+32 (head 2+(L>>4)).
__global__ void __launch_bounds__(256) k_agg1() {
    int wid = (blockIdx.x * blockDim.x + threadIdx.x) >> 5;
    int l = threadIdx.x & 31;
    if (wid >= NN) return;
    const int d = wid;
    const int r0 = g_rowptr[d], r1 = g_rowptr[d + 1];
    float4 ad4 = *(const float4*)&g_ad1[d * H1N];
    const bool lo = (l < 16);
    const float ad_a = lo ? ad4.x : ad4.y;
    const float ad_b = lo ? ad4.z : ad4.w;
    float4 acc0 = make_float4(0.f, 0.f, 0.f, 0.f);
    float4 acc1 = make_float4(0.f, 0.f, 0.f, 0.f);
    float sum0 = 0.f, sum1 = 0.f;
    for (int e = r0; e < r1; e++) {
        int s = g_csrc[e];
        float4 as4 = *(const float4*)&g_as1[s * H1N];
        float e0 = __expf(lrelu02((lo ? as4.x : as4.y) + ad_a));
        float e1 = __expf(lrelu02((lo ? as4.z : as4.w) + ad_b));
        sum0 += e0; sum1 += e1;
        const float4* hp = (const float4*)(g_h1 + (size_t)s * F1);
        float4 v0 = hp[l], v1 = hp[l + 32];
        acc0.x = fmaf(e0, v0.x, acc0.x); acc0.y = fmaf(e0, v0.y, acc0.y);
        acc0.z = fmaf(e0, v0.z, acc0.z); acc0.w = fmaf(e0, v0.w, acc0.w);
        acc1.x = fmaf(e1, v1.x, acc1.x); acc1.y = fmaf(e1, v1.y, acc1.y);
        acc1.z = fmaf(e1, v1.z, acc1.z); acc1.w = fmaf(e1, v1.w, acc1.w);
    }
    float inv0 = 1.f / (sum0 + 1e-16f);
    float inv1 = 1.f / (sum1 + 1e-16f);
    float4* op = (float4*)(g_out1 + (size_t)d * F1);
    op[l]      = make_float4(acc0.x * inv0, acc0.y * inv0, acc0.z * inv0, acc0.w * inv0);
    op[l + 32] = make_float4(acc1.x * inv1, acc1.y * inv1, acc1.z * inv1, acc1.w * inv1);
}

// ---------------- fused CSR gather aggregation, layer 2 ----------------------
// warp per destination node, lane owns 2 channels.
__global__ void __launch_bounds__(256) k_agg2() {
    int wid = (blockIdx.x * blockDim.x + threadIdx.x) >> 5;
    int l = threadIdx.x & 31;
    if (wid >= NN) return;
    const int d = wid;
    const int r0 = g_rowptr[d], r1 = g_rowptr[d + 1];
    const float ad = g_ad2[d];
    float2 acc = make_float2(0.f, 0.f);
    float sum = 0.f;
    for (int e = r0; e < r1; e++) {
        int s = g_csrc[e];
        float ex = __expf(lrelu02(g_as2[s] + ad));
        sum += ex;
        float2 v = ((const float2*)(g_g2 + (size_t)s * HIDC))[l];
        acc.x = fmaf(ex, v.x, acc.x);
        acc.y = fmaf(ex, v.y, acc.y);
    }
    float inv = 1.f / (sum + 1e-16f);
    ((float2*)(g_out2 + (size_t)d * HIDC))[l] = make_float2(acc.x * inv, acc.y * inv);
}

// ---------------- classifier MLP: relu(elu(z+b2)@W3+b3)@W4+b4 ---------------
__global__ void k_mlp(const float* __restrict__ b2,
                      const float* __restrict__ W3, const float* __restrict__ b3,
                      const float* __restrict__ W4, const float* __restrict__ b4,
                      float* __restrict__ out) {
    __shared__ float sW3[64 * 32];
    __shared__ float sb3[32];
    __shared__ float sW4[32 * 2];
    __shared__ float sb4[2];
    __shared__ float sb2[64];
    __shared__ float sz[32][65];
    __shared__ float sh[32][33];
    int t = threadIdx.x;                  // 128 threads, 32 nodes per block
    for (int j = t; j < 2048; j += 128) sW3[j] = W3[j];
    if (t < 32) sb3[t] = b3[t];
    if (t < 64) { sW4[t] = W4[t]; sb2[t] = b2[t]; }
    if (t < 2)  sb4[t] = b4[t];
    __syncthreads();
    int n0 = blockIdx.x * 32;
    for (int j = t; j < 2048; j += 128) {
        int r = j >> 6, c = j & 63;
        int n = n0 + r;
        sz[r][c] = (n < NN) ? eluf(g_out2[(size_t)n * HIDC + c] + sb2[c]) : 0.f;
    }
    __syncthreads();
    for (int j = t; j < 1024; j += 128) {
        int r = j >> 5, hh = j & 31;
        float acc = sb3[hh];
        #pragma unroll
        for (int k = 0; k < 64; k++) acc += sz[r][k] * sW3[k * 32 + hh];
        sh[r][hh] = fmaxf(acc, 0.f);
    }
    __syncthreads();
    if (t < 64) {
        int r = t >> 1, o = t & 1;
        int n = n0 + r;
        if (n < NN) {
            float acc = sb4[o];
            #pragma unroll
            for (int k = 0; k < 32; k++) acc += sh[r][k] * sW4[k * 2 + o];
            out[(size_t)n * 2 + o] = acc;
        }
    }
}

// ---------------- launch -----------------------------------------------------
extern "C" void kernel_launch(void* const* d_in, const int* in_sizes, int n_in,
                              void* d_out, int out_size) {
    const float* x       = (const float*)d_in[0];
    const void*  eidx    = d_in[1];
    const float* W1      = (const float*)d_in[2];
    const float* a_src1  = (const float*)d_in[3];
    const float* a_dst1  = (const float*)d_in[4];
    const float* b1      = (const float*)d_in[5];
    const float* W2      = (const float*)d_in[6];
    const float* a_src2  = (const float*)d_in[7];
    const float* a_dst2  = (const float*)d_in[8];
    const float* b2      = (const float*)d_in[9];
    const float* W3      = (const float*)d_in[10];
    const float* b3      = (const float*)d_in[11];
    const float* W4      = (const float*)d_in[12];
    const float* b4      = (const float*)d_in[13];
    float* out = (float*)d_out;

    // CSR build (multi-block scan)
    k_init0<<<(NN + 255) / 256, 256>>>();
    k_detect<<<(EE + 255) / 256, 256>>>((const unsigned int*)eidx);
    k_hist<<<(ET + 255) / 256, 256>>>((const int*)eidx);
    k_scanA<<<NB, 256>>>();
    k_scanB<<<1, 256>>>();
    k_scanC<<<NB, 256>>>();
    k_place<<<(ET + 255) / 256, 256>>>((const int*)eidx);

    // layer 1
    k_gemm1<<<dim3(F1 / 128, (NN + 127) / 128), 256>>>(x, W1);
    k_attn1<<<(NN + 7) / 8, 256>>>(a_src1, a_dst1);
    k_agg1<<<(NN * 32 + 255) / 256, 256>>>();

    // layer 2 (bias+ELU of layer1 fused into gemm2's A load)
    k_gemm2<<<dim3(HIDC / 64, (NN + 127) / 128), 256>>>(W2, b1);
    k_attn2<<<(NN + 7) / 8, 256>>>(a_src2, a_dst2);
    k_agg2<<<(NN * 32 + 255) / 256, 256>>>();

    // classifier (bias+ELU of layer2 fused into MLP input load)
    k_mlp<<<(NN + 31) / 32, 128>>>(b2, W3, b3, W4, b4, out);
}

// round 12
// speedup vs baseline: 2.0980x; 1.0809x over previous
#include <cuda_runtime.h>

#define NN    50000
#define EE    800000
#define ET    (EE + NN)        // edges + self loops = 850000
#define INDIM 128
#define HIDC  64
#define H1N   4
#define F1    256              // 4 heads * 64

#define SCB   256              // scan chunk (nodes per block)
#define NB    ((NN + SCB - 1) / SCB)   // 196 scan blocks

// ---------------- scratch (device globals; no allocation allowed) ----------
__device__ __align__(16) float g_h1  [NN * F1];    // x @ W1
__device__ __align__(16) float g_out1[NN * F1];    // layer1 aggregated (normalized)
__device__ __align__(16) float g_as1 [NN * H1N];
__device__ __align__(16) float g_ad1 [NN * H1N];
__device__ __align__(16) float g_g2  [NN * HIDC];  // elu(out1+b1) @ W2
__device__ __align__(16) float g_out2[NN * HIDC];  // layer2 aggregated (normalized)
__device__ __align__(16) float g_as2 [NN];
__device__ __align__(16) float g_ad2 [NN];
__device__ int g_rowptr[NN + 1];
__device__ int g_fill[NN];
__device__ int g_bsum[NB];
__device__ int g_csrc[ET];
__device__ int g_is64;

// ---------------- helpers ---------------------------------------------------
__device__ __forceinline__ float lrelu02(float x) { return x > 0.f ? x : 0.2f * x; }
__device__ __forceinline__ float eluf(float x)    { return x > 0.f ? x : (__expf(x) - 1.f); }

// ---------------- CSR build -------------------------------------------------
__global__ void k_init0() {
    int i = blockIdx.x * blockDim.x + threadIdx.x;
    if (i == 0) g_is64 = 1;
    if (i < NN) g_fill[i] = 0;
}

// int64-vs-int32 edge_index detection: if int64, high words of first E entries are 0
__global__ void k_detect(const unsigned int* __restrict__ w) {
    int i = blockIdx.x * blockDim.x + threadIdx.x;
    if (i < EE) {
        if (w[2 * i + 1] != 0u) g_is64 = 0;
    }
}

__global__ void k_hist(const int* __restrict__ w) {
    int i = blockIdx.x * blockDim.x + threadIdx.x;
    if (i >= ET) return;
    int d;
    if (i < EE) d = g_is64 ? w[2 * EE + 2 * i] : w[EE + i];
    else        d = i - EE;
    atomicAdd(&g_fill[d], 1);
}

// ---- multi-block exclusive scan of g_fill -> g_rowptr -----------------------
__global__ void k_scanA() {
    __shared__ int wsum[8];
    const int t = threadIdx.x;            // 256
    const int i = blockIdx.x * SCB + t;
    const int l = t & 31, w = t >> 5;
    int v = (i < NN) ? g_fill[i] : 0;
    int x = v;
    #pragma unroll
    for (int o = 1; o < 32; o <<= 1) {
        int y = __shfl_up_sync(0xFFFFFFFFu, x, o);
        if (l >= o) x += y;
    }
    if (l == 31) wsum[w] = x;
    __syncthreads();
    if (w == 0) {
        int s = (l < 8) ? wsum[l] : 0;
        #pragma unroll
        for (int o = 1; o < 8; o <<= 1) {
            int y = __shfl_up_sync(0xFFFFFFFFu, s, o);
            if (l >= o) s += y;
        }
        if (l < 8) wsum[l] = s;
    }
    __syncthreads();
    int excl = x - v + (w > 0 ? wsum[w - 1] : 0);
    if (i < NN) g_rowptr[i] = excl;
    if (t == 255) g_bsum[blockIdx.x] = excl + v;
}

__global__ void k_scanB() {
    __shared__ int wsum[8];
    const int t = threadIdx.x;            // 256
    const int l = t & 31, w = t >> 5;
    int v = (t < NB) ? g_bsum[t] : 0;
    int x = v;
    #pragma unroll
    for (int o = 1; o < 32; o <<= 1) {
        int y = __shfl_up_sync(0xFFFFFFFFu, x, o);
        if (l >= o) x += y;
    }
    if (l == 31) wsum[w] = x;
    __syncthreads();
    if (w == 0) {
        int s = (l < 8) ? wsum[l] : 0;
        #pragma unroll
        for (int o = 1; o < 8; o <<= 1) {
            int y = __shfl_up_sync(0xFFFFFFFFu, s, o);
            if (l >= o) s += y;
        }
        if (l < 8) wsum[l] = s;
    }
    __syncthreads();
    int excl = x - v + (w > 0 ? wsum[w - 1] : 0);
    if (t < NB) g_bsum[t] = excl;
}

__global__ void k_scanC() {
    const int i = blockIdx.x * SCB + threadIdx.x;
    if (i < NN) {
        int r = g_rowptr[i] + g_bsum[blockIdx.x];
        g_rowptr[i] = r;
        g_fill[i]   = r;
    }
    if (i == 0) g_rowptr[NN] = ET;
}

__global__ void k_place(const int* __restrict__ w) {
    int i = blockIdx.x * blockDim.x + threadIdx.x;
    if (i >= ET) return;
    int s, d;
    if (i < EE) {
        if (g_is64) { s = w[2 * i]; d = w[2 * EE + 2 * i]; }
        else        { s = w[i];     d = w[EE + i]; }
    } else {
        s = d = i - EE;
    }
    int pos = atomicAdd(&g_fill[d], 1);
    g_csrc[pos] = s;
}

// ---------------- double-buffered register-tiled fp32 GEMM -------------------
template <int BN, int TN, bool ACT>
__device__ __forceinline__ void gemm_body(const float* __restrict__ A,
                                          const float* __restrict__ B,
                                          float* __restrict__ C,
                                          int M, int Nc, int K,
                                          const float* __restrict__ bias) {
    constexpr int BM = 128, BK = 16, TM = 8;
    constexpr int NB4 = (BK * BN / 4) / 256;
    __shared__ float As[2][BK][BM + 4];
    __shared__ float Bs[2][BK][BN];
    const int t  = threadIdx.x;
    const int tr = t >> 4;
    const int tc = t & 15;
    const int m0 = blockIdx.y * BM, n0 = blockIdx.x * BN;

    const int ar0 = (2 * t) / 4,     ak0 = ((2 * t)     & 3) * 4;
    const int ar1 = (2 * t + 1) / 4, ak1 = ((2 * t + 1) & 3) * 4;

    float acc[TM][TN] = {};
    float4 av0, av1, bv[NB4];
    const int KT = K / BK;

    auto ldA = [&](int k0, int row, int kq) -> float4 {
        int m = m0 + row;
        float4 v = make_float4(0.f, 0.f, 0.f, 0.f);
        if (m < M) {
            v = *(const float4*)&A[(size_t)m * K + k0 + kq];
            if (ACT) {
                int kc = k0 + kq;
                v.x = eluf(v.x + bias[kc]);
                v.y = eluf(v.y + bias[kc + 1]);
                v.z = eluf(v.z + bias[kc + 2]);
                v.w = eluf(v.w + bias[kc + 3]);
            }
        }
        return v;
    };
    auto ldB = [&](int k0) {
        #pragma unroll
        for (int j = 0; j < NB4; j++) {
            int idx = t + j * 256;
            int row = idx / (BN / 4), c4 = idx % (BN / 4);
            bv[j] = *(const float4*)&B[(size_t)(k0 + row) * Nc + n0 + c4 * 4];
        }
    };
    auto stTile = [&](int nb) {
        As[nb][ak0 + 0][ar0] = av0.x; As[nb][ak0 + 1][ar0] = av0.y;
        As[nb][ak0 + 2][ar0] = av0.z; As[nb][ak0 + 3][ar0] = av0.w;
        As[nb][ak1 + 0][ar1] = av1.x; As[nb][ak1 + 1][ar1] = av1.y;
        As[nb][ak1 + 2][ar1] = av1.z; As[nb][ak1 + 3][ar1] = av1.w;
        #pragma unroll
        for (int j = 0; j < NB4; j++) {
            int idx = t + j * 256;
            int row = idx / (BN / 4), c4 = idx % (BN / 4);
            *(float4*)&Bs[nb][row][c4 * 4] = bv[j];
        }
    };

    av0 = ldA(0, ar0, ak0);
    av1 = ldA(0, ar1, ak1);
    ldB(0);
    stTile(0);
    __syncthreads();

    int buf = 0;
    for (int kt = 0; kt < KT; kt++) {
        const bool next = (kt + 1 < KT);
        if (next) {
            int k0 = (kt + 1) * BK;
            av0 = ldA(k0, ar0, ak0);
            av1 = ldA(k0, ar1, ak1);
            ldB(k0);
        }
        #pragma unroll
        for (int k = 0; k < BK; k++) {
            float a[TM], b[TN];
            #pragma unroll
            for (int iq = 0; iq < TM / 4; iq++) {
                float4 a4 = *(const float4*)&As[buf][k][tr * TM + iq * 4];
                a[iq * 4] = a4.x; a[iq * 4 + 1] = a4.y; a[iq * 4 + 2] = a4.z; a[iq * 4 + 3] = a4.w;
            }
            #pragma unroll
            for (int jq = 0; jq < TN / 4; jq++) {
                float4 b4 = *(const float4*)&Bs[buf][k][tc * TN + jq * 4];
                b[jq * 4] = b4.x; b[jq * 4 + 1] = b4.y; b[jq * 4 + 2] = b4.z; b[jq * 4 + 3] = b4.w;
            }
            #pragma unroll
            for (int ii = 0; ii < TM; ii++)
                #pragma unroll
                for (int jj = 0; jj < TN; jj++)
                    acc[ii][jj] = fmaf(a[ii], b[jj], acc[ii][jj]);
        }
        if (next) stTile(buf ^ 1);
        __syncthreads();
        buf ^= 1;
    }

    #pragma unroll
    for (int ii = 0; ii < TM; ii++) {
        int m = m0 + tr * TM + ii;
        if (m < M) {
            #pragma unroll
            for (int jq = 0; jq < TN / 4; jq++) {
                float4 o = make_float4(acc[ii][jq * 4], acc[ii][jq * 4 + 1],
                                       acc[ii][jq * 4 + 2], acc[ii][jq * 4 + 3]);
                *(float4*)&C[(size_t)m * Nc + n0 + tc * TN + jq * 4] = o;
            }
        }
    }
}

__global__ void __launch_bounds__(256) k_gemm1(const float* __restrict__ x,
                                               const float* __restrict__ W1) {
    gemm_body<128, 8, false>(x, W1, g_h1, NN, F1, INDIM, nullptr);
}
__global__ void __launch_bounds__(256) k_gemm2(const float* __restrict__ W2,
                                               const float* __restrict__ b1) {
    gemm_body<64, 4, true>(g_out1, W2, g_g2, NN, HIDC, F1, b1);
}

// ---------------- attention coefficients ------------------------------------
__global__ void k_attn1(const float* __restrict__ a_src, const float* __restrict__ a_dst) {
    __shared__ float sa[F1], sd[F1];
    int t = threadIdx.x;                 // 256 threads
    sa[t] = a_src[t]; sd[t] = a_dst[t];
    __syncthreads();
    int w = t >> 5, l = t & 31;
    int n = blockIdx.x * 8 + w;
    if (n >= NN) return;
    const float4* hp = (const float4*)(g_h1 + (size_t)n * F1);
    float ss = 0.f, ds = 0.f;
    #pragma unroll
    for (int q = 0; q < 2; q++) {
        float4 v = hp[l * 2 + q];
        int b = l * 8 + q * 4;
        ss += v.x * sa[b] + v.y * sa[b + 1] + v.z * sa[b + 2] + v.w * sa[b + 3];
        ds += v.x * sd[b] + v.y * sd[b + 1] + v.z * sd[b + 2] + v.w * sd[b + 3];
    }
    #pragma unroll
    for (int o = 4; o >= 1; o >>= 1) {
        ss += __shfl_xor_sync(0xFFFFFFFFu, ss, o);
        ds += __shfl_xor_sync(0xFFFFFFFFu, ds, o);
    }
    if ((l & 7) == 0) {
        int h = l >> 3;
        g_as1[n * H1N + h] = ss;
        g_ad1[n * H1N + h] = ds;
    }
}

__global__ void k_attn2(const float* __restrict__ a_src, const float* __restrict__ a_dst) {
    __shared__ float sa[HIDC], sd[HIDC];
    int t = threadIdx.x;                 // 256 threads
    if (t < HIDC) { sa[t] = a_src[t]; sd[t] = a_dst[t]; }
    __syncthreads();
    int w = t >> 5, l = t & 31;
    int n = blockIdx.x * 8 + w;
    if (n >= NN) return;
    const float2* hp = (const float2*)(g_g2 + (size_t)n * HIDC);
    float2 v = hp[l];
    float ss = v.x * sa[2 * l] + v.y * sa[2 * l + 1];
    float ds = v.x * sd[2 * l] + v.y * sd[2 * l + 1];
    #pragma unroll
    for (int o = 16; o >= 1; o >>= 1) {
        ss += __shfl_xor_sync(0xFFFFFFFFu, ss, o);
        ds += __shfl_xor_sync(0xFFFFFFFFu, ds, o);
    }
    if (l == 0) { g_as2[n] = ss; g_ad2[n] = ds; }
}

// ---------------- fused CSR gather aggregation, layer 1 ----------------------
__global__ void __launch_bounds__(256) k_agg1() {
    int wid = (blockIdx.x * blockDim.x + threadIdx.x) >> 5;
    int l = threadIdx.x & 31;
    if (wid >= NN) return;
    const int d = wid;
    const int r0 = g_rowptr[d], r1 = g_rowptr[d + 1];
    float4 ad4 = *(const float4*)&g_ad1[d * H1N];
    const bool lo = (l < 16);
    const float ad_a = lo ? ad4.x : ad4.y;
    const float ad_b = lo ? ad4.z : ad4.w;
    float4 acc0 = make_float4(0.f, 0.f, 0.f, 0.f);
    float4 acc1 = make_float4(0.f, 0.f, 0.f, 0.f);
    float sum0 = 0.f, sum1 = 0.f;
    for (int e = r0; e < r1; e++) {
        int s = g_csrc[e];
        float4 as4 = *(const float4*)&g_as1[s * H1N];
        float e0 = __expf(lrelu02((lo ? as4.x : as4.y) + ad_a));
        float e1 = __expf(lrelu02((lo ? as4.z : as4.w) + ad_b));
        sum0 += e0; sum1 += e1;
        const float4* hp = (const float4*)(g_h1 + (size_t)s * F1);
        float4 v0 = hp[l], v1 = hp[l + 32];
        acc0.x = fmaf(e0, v0.x, acc0.x); acc0.y = fmaf(e0, v0.y, acc0.y);
        acc0.z = fmaf(e0, v0.z, acc0.z); acc0.w = fmaf(e0, v0.w, acc0.w);
        acc1.x = fmaf(e1, v1.x, acc1.x); acc1.y = fmaf(e1, v1.y, acc1.y);
        acc1.z = fmaf(e1, v1.z, acc1.z); acc1.w = fmaf(e1, v1.w, acc1.w);
    }
    float inv0 = 1.f / (sum0 + 1e-16f);
    float inv1 = 1.f / (sum1 + 1e-16f);
    float4* op = (float4*)(g_out1 + (size_t)d * F1);
    op[l]      = make_float4(acc0.x * inv0, acc0.y * inv0, acc0.z * inv0, acc0.w * inv0);
    op[l + 32] = make_float4(acc1.x * inv1, acc1.y * inv1, acc1.z * inv1, acc1.w * inv1);
}

// ---------------- fused CSR gather aggregation, layer 2 ----------------------
__global__ void __launch_bounds__(256) k_agg2() {
    int wid = (blockIdx.x * blockDim.x + threadIdx.x) >> 5;
    int l = threadIdx.x & 31;
    if (wid >= NN) return;
    const int d = wid;
    const int r0 = g_rowptr[d], r1 = g_rowptr[d + 1];
    const float ad = g_ad2[d];
    float2 acc = make_float2(0.f, 0.f);
    float sum = 0.f;
    for (int e = r0; e < r1; e++) {
        int s = g_csrc[e];
        float ex = __expf(lrelu02(g_as2[s] + ad));
        sum += ex;
        float2 v = ((const float2*)(g_g2 + (size_t)s * HIDC))[l];
        acc.x = fmaf(ex, v.x, acc.x);
        acc.y = fmaf(ex, v.y, acc.y);
    }
    float inv = 1.f / (sum + 1e-16f);
    ((float2*)(g_out2 + (size_t)d * HIDC))[l] = make_float2(acc.x * inv, acc.y * inv);
}

// ---------------- classifier MLP: relu(elu(z+b2)@W3+b3)@W4+b4 ---------------
__global__ void k_mlp(const float* __restrict__ b2,
                      const float* __restrict__ W3, const float* __restrict__ b3,
                      const float* __restrict__ W4, const float* __restrict__ b4,
                      float* __restrict__ out) {
    __shared__ float sW3[64 * 32];
    __shared__ float sb3[32];
    __shared__ float sW4[32 * 2];
    __shared__ float sb4[2];
    __shared__ float sb2[64];
    __shared__ float sz[32][65];
    __shared__ float sh[32][33];
    int t = threadIdx.x;                  // 128 threads, 32 nodes per block
    for (int j = t; j < 2048; j += 128) sW3[j] = W3[j];
    if (t < 32) sb3[t] = b3[t];
    if (t < 64) { sW4[t] = W4[t]; sb2[t] = b2[t]; }
    if (t < 2)  sb4[t] = b4[t];
    __syncthreads();
    int n0 = blockIdx.x * 32;
    for (int j = t; j < 2048; j += 128) {
        int r = j >> 6, c = j & 63;
        int n = n0 + r;
        sz[r][c] = (n < NN) ? eluf(g_out2[(size_t)n * HIDC + c] + sb2[c]) : 0.f;
    }
    __syncthreads();
    for (int j = t; j < 1024; j += 128) {
        int r = j >> 5, hh = j & 31;
        float acc = sb3[hh];
        #pragma unroll
        for (int k = 0; k < 64; k++) acc += sz[r][k] * sW3[k * 32 + hh];
        sh[r][hh] = fmaxf(acc, 0.f);
    }
    __syncthreads();
    if (t < 64) {
        int r = t >> 1, o = t & 1;
        int n = n0 + r;
        if (n < NN) {
            float acc = sb4[o];
            #pragma unroll
            for (int k = 0; k < 32; k++) acc += sh[r][k] * sW4[k * 2 + o];
            out[(size_t)n * 2 + o] = acc;
        }
    }
}

// ---------------- launch -----------------------------------------------------
extern "C" void kernel_launch(void* const* d_in, const int* in_sizes, int n_in,
                              void* d_out, int out_size) {
    const float* x       = (const float*)d_in[0];
    const void*  eidx    = d_in[1];
    const float* W1      = (const float*)d_in[2];
    const float* a_src1  = (const float*)d_in[3];
    const float* a_dst1  = (const float*)d_in[4];
    const float* b1      = (const float*)d_in[5];
    const float* W2      = (const float*)d_in[6];
    const float* a_src2  = (const float*)d_in[7];
    const float* a_dst2  = (const float*)d_in[8];
    const float* b2      = (const float*)d_in[9];
    const float* W3      = (const float*)d_in[10];
    const float* b3      = (const float*)d_in[11];
    const float* W4      = (const float*)d_in[12];
    const float* b4      = (const float*)d_in[13];
    float* out = (float*)d_out;

    // One-time resource init (host objects only; same work every call).
    static cudaStream_t s2 = nullptr;
    static cudaEvent_t evStart = nullptr, evCsr = nullptr;
    if (s2 == nullptr) {
        cudaStreamCreateWithFlags(&s2, cudaStreamNonBlocking);
        cudaEventCreateWithFlags(&evStart, cudaEventDisableTiming);
        cudaEventCreateWithFlags(&evCsr, cudaEventDisableTiming);
    }

    // Fork: CSR build on side stream, overlapped with gemm1+attn1.
    cudaEventRecord(evStart, 0);
    cudaStreamWaitEvent(s2, evStart, 0);

    k_init0<<<(NN + 255) / 256, 256, 0, s2>>>();
    k_detect<<<(EE + 255) / 256, 256, 0, s2>>>((const unsigned int*)eidx);
    k_hist<<<(ET + 255) / 256, 256, 0, s2>>>((const int*)eidx);
    k_scanA<<<NB, 256, 0, s2>>>();
    k_scanB<<<1, 256, 0, s2>>>();
    k_scanC<<<NB, 256, 0, s2>>>();
    k_place<<<(ET + 255) / 256, 256, 0, s2>>>((const int*)eidx);
    cudaEventRecord(evCsr, s2);

    // main stream: feature transform + attention coefficients (independent of CSR)
    k_gemm1<<<dim3(F1 / 128, (NN + 127) / 128), 256>>>(x, W1);
    k_attn1<<<(NN + 7) / 8, 256>>>(a_src1, a_dst1);

    // join before aggregation
    cudaStreamWaitEvent(0, evCsr, 0);
    k_agg1<<<(NN * 32 + 255) / 256, 256>>>();

    // layer 2 (bias+ELU of layer1 fused into gemm2's A load)
    k_gemm2<<<dim3(HIDC / 64, (NN + 127) / 128), 256>>>(W2, b1);
    k_attn2<<<(NN + 7) / 8, 256>>>(a_src2, a_dst2);
    k_agg2<<<(NN * 32 + 255) / 256, 256>>>();

    // classifier (bias+ELU of layer2 fused into MLP input load)
    k_mlp<<<(NN + 31) / 32, 128>>>(b2, W3, b3, W4, b4, out);
}

// round 15
// speedup vs baseline: 2.1113x; 1.0063x over previous
#include <cuda_runtime.h>

#define NN    50000
#define EE    800000
#define ET    (EE + NN)        // edges + self loops = 850000
#define INDIM 128
#define HIDC  64
#define H1N   4
#define F1    256              // 4 heads * 64

#define SCB   256              // scan chunk (nodes per block)
#define NB    ((NN + SCB - 1) / SCB)   // 196 scan blocks

// ---------------- scratch (device globals; no allocation allowed) ----------
__device__ __align__(16) float g_h1  [NN * F1];    // x @ W1
__device__ __align__(16) float g_out1[NN * F1];    // layer1 aggregated (normalized)
__device__ __align__(16) float g_as1 [NN * H1N];
__device__ __align__(16) float g_ad1 [NN * H1N];
__device__ __align__(16) float g_g2  [NN * HIDC];  // elu(out1+b1) @ W2
__device__ __align__(16) float g_out2[NN * HIDC];  // layer2 aggregated (normalized)
__device__ __align__(16) float g_as2 [NN];
__device__ __align__(16) float g_ad2 [NN];
__device__ int g_rowptr[NN + 1];
__device__ int g_fill[NN];
__device__ int g_bsum[NB];
__device__ int g_csrc[ET];
__device__ int g_is64;

// ---------------- helpers ---------------------------------------------------
__device__ __forceinline__ float lrelu02(float x) { return x > 0.f ? x : 0.2f * x; }
__device__ __forceinline__ float eluf(float x)    { return x > 0.f ? x : (__expf(x) - 1.f); }

// ---------------- CSR build -------------------------------------------------
__global__ void k_init0() {
    int i = blockIdx.x * blockDim.x + threadIdx.x;
    if (i == 0) g_is64 = 1;
    if (i < NN) g_fill[i] = 0;
}

// int64-vs-int32 edge_index detection: if int64, high words of first E entries are 0
__global__ void k_detect(const unsigned int* __restrict__ w) {
    int i = blockIdx.x * blockDim.x + threadIdx.x;
    if (i < EE) {
        if (w[2 * i + 1] != 0u) g_is64 = 0;
    }
}

__global__ void k_hist(const int* __restrict__ w) {
    int i = blockIdx.x * blockDim.x + threadIdx.x;
    if (i >= ET) return;
    int d;
    if (i < EE) d = g_is64 ? w[2 * EE + 2 * i] : w[EE + i];
    else        d = i - EE;
    atomicAdd(&g_fill[d], 1);
}

// ---- multi-block exclusive scan of g_fill -> g_rowptr -----------------------
__global__ void k_scanA() {
    __shared__ int wsum[8];
    const int t = threadIdx.x;            // 256
    const int i = blockIdx.x * SCB + t;
    const int l = t & 31, w = t >> 5;
    int v = (i < NN) ? g_fill[i] : 0;
    int x = v;
    #pragma unroll
    for (int o = 1; o < 32; o <<= 1) {
        int y = __shfl_up_sync(0xFFFFFFFFu, x, o);
        if (l >= o) x += y;
    }
    if (l == 31) wsum[w] = x;
    __syncthreads();
    if (w == 0) {
        int s = (l < 8) ? wsum[l] : 0;
        #pragma unroll
        for (int o = 1; o < 8; o <<= 1) {
            int y = __shfl_up_sync(0xFFFFFFFFu, s, o);
            if (l >= o) s += y;
        }
        if (l < 8) wsum[l] = s;
    }
    __syncthreads();
    int excl = x - v + (w > 0 ? wsum[w - 1] : 0);
    if (i < NN) g_rowptr[i] = excl;
    if (t == 255) g_bsum[blockIdx.x] = excl + v;
}

__global__ void k_scanB() {
    __shared__ int wsum[8];
    const int t = threadIdx.x;            // 256
    const int l = t & 31, w = t >> 5;
    int v = (t < NB) ? g_bsum[t] : 0;
    int x = v;
    #pragma unroll
    for (int o = 1; o < 32; o <<= 1) {
        int y = __shfl_up_sync(0xFFFFFFFFu, x, o);
        if (l >= o) x += y;
    }
    if (l == 31) wsum[w] = x;
    __syncthreads();
    if (w == 0) {
        int s = (l < 8) ? wsum[l] : 0;
        #pragma unroll
        for (int o = 1; o < 8; o <<= 1) {
            int y = __shfl_up_sync(0xFFFFFFFFu, s, o);
            if (l >= o) s += y;
        }
        if (l < 8) wsum[l] = s;
    }
    __syncthreads();
    int excl = x - v + (w > 0 ? wsum[w - 1] : 0);
    if (t < NB) g_bsum[t] = excl;
}

__global__ void k_scanC() {
    const int i = blockIdx.x * SCB + threadIdx.x;
    if (i < NN) {
        int r = g_rowptr[i] + g_bsum[blockIdx.x];
        g_rowptr[i] = r;
        g_fill[i]   = r;
    }
    if (i == 0) g_rowptr[NN] = ET;
}

__global__ void k_place(const int* __restrict__ w) {
    int i = blockIdx.x * blockDim.x + threadIdx.x;
    if (i >= ET) return;
    int s, d;
    if (i < EE) {
        if (g_is64) { s = w[2 * i]; d = w[2 * EE + 2 * i]; }
        else        { s = w[i];     d = w[EE + i]; }
    } else {
        s = d = i - EE;
    }
    int pos = atomicAdd(&g_fill[d], 1);
    g_csrc[pos] = s;
}

// ---------------- double-buffered register-tiled fp32 GEMM -------------------
template <int BN, int TN, bool ACT>
__device__ __forceinline__ void gemm_body(const float* __restrict__ A,
                                          const float* __restrict__ B,
                                          float* __restrict__ C,
                                          int M, int Nc, int K,
                                          const float* __restrict__ bias) {
    constexpr int BM = 128, BK = 16, TM = 8;
    constexpr int NB4 = (BK * BN / 4) / 256;
    __shared__ float As[2][BK][BM + 4];
    __shared__ float Bs[2][BK][BN];
    const int t  = threadIdx.x;
    const int tr = t >> 4;
    const int tc = t & 15;
    const int m0 = blockIdx.y * BM, n0 = blockIdx.x * BN;

    const int ar0 = (2 * t) / 4,     ak0 = ((2 * t)     & 3) * 4;
    const int ar1 = (2 * t + 1) / 4, ak1 = ((2 * t + 1) & 3) * 4;

    float acc[TM][TN] = {};
    float4 av0, av1, bv[NB4];
    const int KT = K / BK;

    auto ldA = [&](int k0, int row, int kq) -> float4 {
        int m = m0 + row;
        float4 v = make_float4(0.f, 0.f, 0.f, 0.f);
        if (m < M) {
            v = *(const float4*)&A[(size_t)m * K + k0 + kq];
            if (ACT) {
                int kc = k0 + kq;
                v.x = eluf(v.x + bias[kc]);
                v.y = eluf(v.y + bias[kc + 1]);
                v.z = eluf(v.z + bias[kc + 2]);
                v.w = eluf(v.w + bias[kc + 3]);
            }
        }
        return v;
    };
    auto ldB = [&](int k0) {
        #pragma unroll
        for (int j = 0; j < NB4; j++) {
            int idx = t + j * 256;
            int row = idx / (BN / 4), c4 = idx % (BN / 4);
            bv[j] = *(const float4*)&B[(size_t)(k0 + row) * Nc + n0 + c4 * 4];
        }
    };
    auto stTile = [&](int nb) {
        As[nb][ak0 + 0][ar0] = av0.x; As[nb][ak0 + 1][ar0] = av0.y;
        As[nb][ak0 + 2][ar0] = av0.z; As[nb][ak0 + 3][ar0] = av0.w;
        As[nb][ak1 + 0][ar1] = av1.x; As[nb][ak1 + 1][ar1] = av1.y;
        As[nb][ak1 + 2][ar1] = av1.z; As[nb][ak1 + 3][ar1] = av1.w;
        #pragma unroll
        for (int j = 0; j < NB4; j++) {
            int idx = t + j * 256;
            int row = idx / (BN / 4), c4 = idx % (BN / 4);
            *(float4*)&Bs[nb][row][c4 * 4] = bv[j];
        }
    };

    av0 = ldA(0, ar0, ak0);
    av1 = ldA(0, ar1, ak1);
    ldB(0);
    stTile(0);
    __syncthreads();

    int buf = 0;
    for (int kt = 0; kt < KT; kt++) {
        const bool next = (kt + 1 < KT);
        if (next) {
            int k0 = (kt + 1) * BK;
            av0 = ldA(k0, ar0, ak0);
            av1 = ldA(k0, ar1, ak1);
            ldB(k0);
        }
        #pragma unroll
        for (int k = 0; k < BK; k++) {
            float a[TM], b[TN];
            #pragma unroll
            for (int iq = 0; iq < TM / 4; iq++) {
                float4 a4 = *(const float4*)&As[buf][k][tr * TM + iq * 4];
                a[iq * 4] = a4.x; a[iq * 4 + 1] = a4.y; a[iq * 4 + 2] = a4.z; a[iq * 4 + 3] = a4.w;
            }
            #pragma unroll
            for (int jq = 0; jq < TN / 4; jq++) {
                float4 b4 = *(const float4*)&Bs[buf][k][tc * TN + jq * 4];
                b[jq * 4] = b4.x; b[jq * 4 + 1] = b4.y; b[jq * 4 + 2] = b4.z; b[jq * 4 + 3] = b4.w;
            }
            #pragma unroll
            for (int ii = 0; ii < TM; ii++)
                #pragma unroll
                for (int jj = 0; jj < TN; jj++)
                    acc[ii][jj] = fmaf(a[ii], b[jj], acc[ii][jj]);
        }
        if (next) stTile(buf ^ 1);
        __syncthreads();
        buf ^= 1;
    }

    #pragma unroll
    for (int ii = 0; ii < TM; ii++) {
        int m = m0 + tr * TM + ii;
        if (m < M) {
            #pragma unroll
            for (int jq = 0; jq < TN / 4; jq++) {
                float4 o = make_float4(acc[ii][jq * 4], acc[ii][jq * 4 + 1],
                                       acc[ii][jq * 4 + 2], acc[ii][jq * 4 + 3]);
                *(float4*)&C[(size_t)m * Nc + n0 + tc * TN + jq * 4] = o;
            }
        }
    }
}

__global__ void __launch_bounds__(256) k_gemm1(const float* __restrict__ x,
                                               const float* __restrict__ W1) {
    gemm_body<128, 8, false>(x, W1, g_h1, NN, F1, INDIM, nullptr);
}
__global__ void __launch_bounds__(256) k_gemm2(const float* __restrict__ W2,
                                               const float* __restrict__ b1) {
    gemm_body<64, 4, true>(g_out1, W2, g_g2, NN, HIDC, F1, b1);
}

// ---------------- attention coefficients ------------------------------------
__global__ void k_attn1(const float* __restrict__ a_src, const float* __restrict__ a_dst) {
    __shared__ float sa[F1], sd[F1];
    int t = threadIdx.x;                 // 256 threads
    sa[t] = a_src[t]; sd[t] = a_dst[t];
    __syncthreads();
    int w = t >> 5, l = t & 31;
    int n = blockIdx.x * 8 + w;
    if (n >= NN) return;
    const float4* hp = (const float4*)(g_h1 + (size_t)n * F1);
    float ss = 0.f, ds = 0.f;
    #pragma unroll
    for (int q = 0; q < 2; q++) {
        float4 v = hp[l * 2 + q];
        int b = l * 8 + q * 4;
        ss += v.x * sa[b] + v.y * sa[b + 1] + v.z * sa[b + 2] + v.w * sa[b + 3];
        ds += v.x * sd[b] + v.y * sd[b + 1] + v.z * sd[b + 2] + v.w * sd[b + 3];
    }
    #pragma unroll
    for (int o = 4; o >= 1; o >>= 1) {
        ss += __shfl_xor_sync(0xFFFFFFFFu, ss, o);
        ds += __shfl_xor_sync(0xFFFFFFFFu, ds, o);
    }
    if ((l & 7) == 0) {
        int h = l >> 3;
        g_as1[n * H1N + h] = ss;
        g_ad1[n * H1N + h] = ds;
    }
}

__global__ void k_attn2(const float* __restrict__ a_src, const float* __restrict__ a_dst) {
    __shared__ float sa[HIDC], sd[HIDC];
    int t = threadIdx.x;                 // 256 threads
    if (t < HIDC) { sa[t] = a_src[t]; sd[t] = a_dst[t]; }
    __syncthreads();
    int w = t >> 5, l = t & 31;
    int n = blockIdx.x * 8 + w;
    if (n >= NN) return;
    const float2* hp = (const float2*)(g_g2 + (size_t)n * HIDC);
    float2 v = hp[l];
    float ss = v.x * sa[2 * l] + v.y * sa[2 * l + 1];
    float ds = v.x * sd[2 * l] + v.y * sd[2 * l + 1];
    #pragma unroll
    for (int o = 16; o >= 1; o >>= 1) {
        ss += __shfl_xor_sync(0xFFFFFFFFu, ss, o);
        ds += __shfl_xor_sync(0xFFFFFFFFu, ds, o);
    }
    if (l == 0) { g_as2[n] = ss; g_ad2[n] = ds; }
}

// ---------------- fused CSR gather aggregation, layer 1 ----------------------
// warp per destination node, 4-edge software pipeline for MLP.
__global__ void __launch_bounds__(256) k_agg1() {
    int wid = (blockIdx.x * blockDim.x + threadIdx.x) >> 5;
    int l = threadIdx.x & 31;
    if (wid >= NN) return;
    const int d = wid;
    const int r0 = g_rowptr[d], r1 = g_rowptr[d + 1];
    float4 ad4 = *(const float4*)&g_ad1[d * H1N];
    const bool lo = (l < 16);
    const float ad_a = lo ? ad4.x : ad4.y;
    const float ad_b = lo ? ad4.z : ad4.w;
    float4 acc0 = make_float4(0.f, 0.f, 0.f, 0.f);
    float4 acc1 = make_float4(0.f, 0.f, 0.f, 0.f);
    float sum0 = 0.f, sum1 = 0.f;

    int e = r0;
    for (; e + 4 <= r1; e += 4) {
        // issue all independent loads first
        const int s0 = g_csrc[e], s1 = g_csrc[e + 1], s2 = g_csrc[e + 2], s3 = g_csrc[e + 3];
        float4 A0 = *(const float4*)&g_as1[s0 * H1N];
        float4 A1 = *(const float4*)&g_as1[s1 * H1N];
        float4 A2 = *(const float4*)&g_as1[s2 * H1N];
        float4 A3 = *(const float4*)&g_as1[s3 * H1N];
        const float4* h0 = (const float4*)(g_h1 + (size_t)s0 * F1);
        const float4* h1 = (const float4*)(g_h1 + (size_t)s1 * F1);
        const float4* h2 = (const float4*)(g_h1 + (size_t)s2 * F1);
        const float4* h3 = (const float4*)(g_h1 + (size_t)s3 * F1);
        float4 u00 = h0[l], u01 = h0[l + 32];
        float4 u10 = h1[l], u11 = h1[l + 32];
        float4 u20 = h2[l], u21 = h2[l + 32];
        float4 u30 = h3[l], u31 = h3[l + 32];

        float e00 = __expf(lrelu02((lo ? A0.x : A0.y) + ad_a));
        float e01 = __expf(lrelu02((lo ? A0.z : A0.w) + ad_b));
        float e10 = __expf(lrelu02((lo ? A1.x : A1.y) + ad_a));
        float e11 = __expf(lrelu02((lo ? A1.z : A1.w) + ad_b));
        float e20 = __expf(lrelu02((lo ? A2.x : A2.y) + ad_a));
        float e21 = __expf(lrelu02((lo ? A2.z : A2.w) + ad_b));
        float e30 = __expf(lrelu02((lo ? A3.x : A3.y) + ad_a));
        float e31 = __expf(lrelu02((lo ? A3.z : A3.w) + ad_b));
        sum0 += (e00 + e10) + (e20 + e30);
        sum1 += (e01 + e11) + (e21 + e31);

        acc0.x = fmaf(e00, u00.x, acc0.x); acc0.y = fmaf(e00, u00.y, acc0.y);
        acc0.z = fmaf(e00, u00.z, acc0.z); acc0.w = fmaf(e00, u00.w, acc0.w);
        acc1.x = fmaf(e01, u01.x, acc1.x); acc1.y = fmaf(e01, u01.y, acc1.y);
        acc1.z = fmaf(e01, u01.z, acc1.z); acc1.w = fmaf(e01, u01.w, acc1.w);
        acc0.x = fmaf(e10, u10.x, acc0.x); acc0.y = fmaf(e10, u10.y, acc0.y);
        acc0.z = fmaf(e10, u10.z, acc0.z); acc0.w = fmaf(e10, u10.w, acc0.w);
        acc1.x = fmaf(e11, u11.x, acc1.x); acc1.y = fmaf(e11, u11.y, acc1.y);
        acc1.z = fmaf(e11, u11.z, acc1.z); acc1.w = fmaf(e11, u11.w, acc1.w);
        acc0.x = fmaf(e20, u20.x, acc0.x); acc0.y = fmaf(e20, u20.y, acc0.y);
        acc0.z = fmaf(e20, u20.z, acc0.z); acc0.w = fmaf(e20, u20.w, acc0.w);
        acc1.x = fmaf(e21, u21.x, acc1.x); acc1.y = fmaf(e21, u21.y, acc1.y);
        acc1.z = fmaf(e21, u21.z, acc1.z); acc1.w = fmaf(e21, u21.w, acc1.w);
        acc0.x = fmaf(e30, u30.x, acc0.x); acc0.y = fmaf(e30, u30.y, acc0.y);
        acc0.z = fmaf(e30, u30.z, acc0.z); acc0.w = fmaf(e30, u30.w, acc0.w);
        acc1.x = fmaf(e31, u31.x, acc1.x); acc1.y = fmaf(e31, u31.y, acc1.y);
        acc1.z = fmaf(e31, u31.z, acc1.z); acc1.w = fmaf(e31, u31.w, acc1.w);
    }
    for (; e < r1; e++) {
        int s = g_csrc[e];
        float4 as4 = *(const float4*)&g_as1[s * H1N];
        float e0 = __expf(lrelu02((lo ? as4.x : as4.y) + ad_a));
        float e1 = __expf(lrelu02((lo ? as4.z : as4.w) + ad_b));
        sum0 += e0; sum1 += e1;
        const float4* hp = (const float4*)(g_h1 + (size_t)s * F1);
        float4 v0 = hp[l], v1 = hp[l + 32];
        acc0.x = fmaf(e0, v0.x, acc0.x); acc0.y = fmaf(e0, v0.y, acc0.y);
        acc0.z = fmaf(e0, v0.z, acc0.z); acc0.w = fmaf(e0, v0.w, acc0.w);
        acc1.x = fmaf(e1, v1.x, acc1.x); acc1.y = fmaf(e1, v1.y, acc1.y);
        acc1.z = fmaf(e1, v1.z, acc1.z); acc1.w = fmaf(e1, v1.w, acc1.w);
    }
    float inv0 = 1.f / (sum0 + 1e-16f);
    float inv1 = 1.f / (sum1 + 1e-16f);
    float4* op = (float4*)(g_out1 + (size_t)d * F1);
    op[l]      = make_float4(acc0.x * inv0, acc0.y * inv0, acc0.z * inv0, acc0.w * inv0);
    op[l + 32] = make_float4(acc1.x * inv1, acc1.y * inv1, acc1.z * inv1, acc1.w * inv1);
}

// ---------------- fused CSR gather aggregation, layer 2 ----------------------
// warp per destination node, 4-edge software pipeline.
__global__ void __launch_bounds__(256) k_agg2() {
    int wid = (blockIdx.x * blockDim.x + threadIdx.x) >> 5;
    int l = threadIdx.x & 31;
    if (wid >= NN) return;
    const int d = wid;
    const int r0 = g_rowptr[d], r1 = g_rowptr[d + 1];
    const float ad = g_ad2[d];
    float2 acc = make_float2(0.f, 0.f);
    float sum = 0.f;

    int e = r0;
    for (; e + 4 <= r1; e += 4) {
        const int s0 = g_csrc[e], s1 = g_csrc[e + 1], s2 = g_csrc[e + 2], s3 = g_csrc[e + 3];
        float a0 = g_as2[s0], a1 = g_as2[s1], a2 = g_as2[s2], a3 = g_as2[s3];
        float2 v0 = ((const float2*)(g_g2 + (size_t)s0 * HIDC))[l];
        float2 v1 = ((const float2*)(g_g2 + (size_t)s1 * HIDC))[l];
        float2 v2 = ((const float2*)(g_g2 + (size_t)s2 * HIDC))[l];
        float2 v3 = ((const float2*)(g_g2 + (size_t)s3 * HIDC))[l];
        float x0 = __expf(lrelu02(a0 + ad));
        float x1 = __expf(lrelu02(a1 + ad));
        float x2 = __expf(lrelu02(a2 + ad));
        float x3 = __expf(lrelu02(a3 + ad));
        sum += (x0 + x1) + (x2 + x3);
        acc.x = fmaf(x0, v0.x, acc.x); acc.y = fmaf(x0, v0.y, acc.y);
        acc.x = fmaf(x1, v1.x, acc.x); acc.y = fmaf(x1, v1.y, acc.y);
        acc.x = fmaf(x2, v2.x, acc.x); acc.y = fmaf(x2, v2.y, acc.y);
        acc.x = fmaf(x3, v3.x, acc.x); acc.y = fmaf(x3, v3.y, acc.y);
    }
    for (; e < r1; e++) {
        int s = g_csrc[e];
        float ex = __expf(lrelu02(g_as2[s] + ad));
        sum += ex;
        float2 v = ((const float2*)(g_g2 + (size_t)s * HIDC))[l];
        acc.x = fmaf(ex, v.x, acc.x);
        acc.y = fmaf(ex, v.y, acc.y);
    }
    float inv = 1.f / (sum + 1e-16f);
    ((float2*)(g_out2 + (size_t)d * HIDC))[l] = make_float2(acc.x * inv, acc.y * inv);
}

// ---------------- classifier MLP: relu(elu(z+b2)@W3+b3)@W4+b4 ---------------
__global__ void k_mlp(const float* __restrict__ b2,
                      const float* __restrict__ W3, const float* __restrict__ b3,
                      const float* __restrict__ W4, const float* __restrict__ b4,
                      float* __restrict__ out) {
    __shared__ float sW3[64 * 32];
    __shared__ float sb3[32];
    __shared__ float sW4[32 * 2];
    __shared__ float sb4[2];
    __shared__ float sb2[64];
    __shared__ float sz[32][65];
    __shared__ float sh[32][33];
    int t = threadIdx.x;                  // 128 threads, 32 nodes per block
    for (int j = t; j < 2048; j += 128) sW3[j] = W3[j];
    if (t < 32) sb3[t] = b3[t];
    if (t < 64) { sW4[t] = W4[t]; sb2[t] = b2[t]; }
    if (t < 2)  sb4[t] = b4[t];
    __syncthreads();
    int n0 = blockIdx.x * 32;
    for (int j = t; j < 2048; j += 128) {
        int r = j >> 6, c = j & 63;
        int n = n0 + r;
        sz[r][c] = (n < NN) ? eluf(g_out2[(size_t)n * HIDC + c] + sb2[c]) : 0.f;
    }
    __syncthreads();
    for (int j = t; j < 1024; j += 128) {
        int r = j >> 5, hh = j & 31;
        float acc = sb3[hh];
        #pragma unroll
        for (int k = 0; k < 64; k++) acc += sz[r][k] * sW3[k * 32 + hh];
        sh[r][hh] = fmaxf(acc, 0.f);
    }
    __syncthreads();
    if (t < 64) {
        int r = t >> 1, o = t & 1;
        int n = n0 + r;
        if (n < NN) {
            float acc = sb4[o];
            #pragma unroll
            for (int k = 0; k < 32; k++) acc += sh[r][k] * sW4[k * 2 + o];
            out[(size_t)n * 2 + o] = acc;
        }
    }
}

// ---------------- launch -----------------------------------------------------
extern "C" void kernel_launch(void* const* d_in, const int* in_sizes, int n_in,
                              void* d_out, int out_size) {
    const float* x       = (const float*)d_in[0];
    const void*  eidx    = d_in[1];
    const float* W1      = (const float*)d_in[2];
    const float* a_src1  = (const float*)d_in[3];
    const float* a_dst1  = (const float*)d_in[4];
    const float* b1      = (const float*)d_in[5];
    const float* W2      = (const float*)d_in[6];
    const float* a_src2  = (const float*)d_in[7];
    const float* a_dst2  = (const float*)d_in[8];
    const float* b2      = (const float*)d_in[9];
    const float* W3      = (const float*)d_in[10];
    const float* b3      = (const float*)d_in[11];
    const float* W4      = (const float*)d_in[12];
    const float* b4      = (const float*)d_in[13];
    float* out = (float*)d_out;

    // One-time resource init (host objects only; same work every call).
    static cudaStream_t s2 = nullptr;
    static cudaEvent_t evStart = nullptr, evCsr = nullptr;
    if (s2 == nullptr) {
        cudaStreamCreateWithFlags(&s2, cudaStreamNonBlocking);
        cudaEventCreateWithFlags(&evStart, cudaEventDisableTiming);
        cudaEventCreateWithFlags(&evCsr, cudaEventDisableTiming);
    }

    // Fork: CSR build on side stream, overlapped with gemm1+attn1.
    cudaEventRecord(evStart, 0);
    cudaStreamWaitEvent(s2, evStart, 0);

    k_init0<<<(NN + 255) / 256, 256, 0, s2>>>();
    k_detect<<<(EE + 255) / 256, 256, 0, s2>>>((const unsigned int*)eidx);
    k_hist<<<(ET + 255) / 256, 256, 0, s2>>>((const int*)eidx);
    k_scanA<<<NB, 256, 0, s2>>>();
    k_scanB<<<1, 256, 0, s2>>>();
    k_scanC<<<NB, 256, 0, s2>>>();
    k_place<<<(ET + 255) / 256, 256, 0, s2>>>((const int*)eidx);
    cudaEventRecord(evCsr, s2);

    // main stream: feature transform + attention coefficients (independent of CSR)
    k_gemm1<<<dim3(F1 / 128, (NN + 127) / 128), 256>>>(x, W1);
    k_attn1<<<(NN + 7) / 8, 256>>>(a_src1, a_dst1);

    // join before aggregation
    cudaStreamWaitEvent(0, evCsr, 0);
    k_agg1<<<(NN * 32 + 255) / 256, 256>>>();

    // layer 2 (bias+ELU of layer1 fused into gemm2's A load)
    k_gemm2<<<dim3(HIDC / 64, (NN + 127) / 128), 256>>>(W2, b1);
    k_attn2<<<(NN + 7) / 8, 256>>>(a_src2, a_dst2);
    k_agg2<<<(NN * 32 + 255) / 256, 256>>>();

    // classifier (bias+ELU of layer2 fused into MLP input load)
    k_mlp<<<(NN + 31) / 32, 128>>>(b2, W3, b3, W4, b4, out);
}

// round 17
// speedup vs baseline: 2.1397x; 1.0134x over previous
#include <cuda_runtime.h>
#include <cstdint>

#define NN    50000
#define EE    800000
#define ET    (EE + NN)        // edges + self loops = 850000
#define INDIM 128
#define HIDC  64
#define H1N   4
#define F1    256              // 4 heads * 64

#define SCB   256              // scan chunk (nodes per block)
#define NB    ((NN + SCB - 1) / SCB)   // 196 scan blocks

// ---------------- scratch (device globals; no allocation allowed) ----------
__device__ __align__(16) float g_h1  [NN * F1];    // x @ W1
__device__ __align__(16) float g_out1[NN * F1];    // layer1 aggregated (normalized)
__device__ __align__(16) float g_as1 [NN * H1N];
__device__ __align__(16) float g_ad1 [NN * H1N];
__device__ __align__(16) float g_g2  [NN * HIDC];  // elu(out1+b1) @ W2
__device__ __align__(16) float g_out2[NN * HIDC];  // layer2 aggregated (normalized)
__device__ __align__(16) float g_as2 [NN];
__device__ __align__(16) float g_ad2 [NN];
__device__ int g_rowptr[NN + 1];
__device__ int g_fill[NN];
__device__ int g_bsum[NB];
__device__ int g_csrc[ET];
__device__ int g_is64;

// ---------------- helpers ---------------------------------------------------
__device__ __forceinline__ float lrelu02(float x) { return x > 0.f ? x : 0.2f * x; }
__device__ __forceinline__ float eluf(float x)    { return x > 0.f ? x : (__expf(x) - 1.f); }

__device__ __forceinline__ uint32_t tf32hi(float x) {
    uint32_t r;
    asm("cvt.rna.tf32.f32 %0, %1;" : "=r"(r) : "f"(x));
    return r;
}

__device__ __forceinline__ void mma_tf32(float4& d,
                                         uint32_t a0, uint32_t a1, uint32_t a2, uint32_t a3,
                                         uint32_t b0, uint32_t b1) {
    asm volatile(
        "mma.sync.aligned.m16n8k8.row.col.f32.tf32.tf32.f32 "
        "{%0,%1,%2,%3}, {%4,%5,%6,%7}, {%8,%9}, {%0,%1,%2,%3};"
        : "+f"(d.x), "+f"(d.y), "+f"(d.z), "+f"(d.w)
        : "r"(a0), "r"(a1), "r"(a2), "r"(a3), "r"(b0), "r"(b1));
}

// ---------------- CSR build -------------------------------------------------
__global__ void k_init0() {
    int i = blockIdx.x * blockDim.x + threadIdx.x;
    if (i == 0) g_is64 = 1;
    if (i < NN) g_fill[i] = 0;
}

// int64-vs-int32 edge_index detection: if int64, high words of first E entries are 0
__global__ void k_detect(const unsigned int* __restrict__ w) {
    int i = blockIdx.x * blockDim.x + threadIdx.x;
    if (i < EE) {
        if (w[2 * i + 1] != 0u) g_is64 = 0;
    }
}

__global__ void k_hist(const int* __restrict__ w) {
    int i = blockIdx.x * blockDim.x + threadIdx.x;
    if (i >= ET) return;
    int d;
    if (i < EE) d = g_is64 ? w[2 * EE + 2 * i] : w[EE + i];
    else        d = i - EE;
    atomicAdd(&g_fill[d], 1);
}

// ---- multi-block exclusive scan of g_fill -> g_rowptr -----------------------
__global__ void k_scanA() {
    __shared__ int wsum[8];
    const int t = threadIdx.x;            // 256
    const int i = blockIdx.x * SCB + t;
    const int l = t & 31, w = t >> 5;
    int v = (i < NN) ? g_fill[i] : 0;
    int x = v;
    #pragma unroll
    for (int o = 1; o < 32; o <<= 1) {
        int y = __shfl_up_sync(0xFFFFFFFFu, x, o);
        if (l >= o) x += y;
    }
    if (l == 31) wsum[w] = x;
    __syncthreads();
    if (w == 0) {
        int s = (l < 8) ? wsum[l] : 0;
        #pragma unroll
        for (int o = 1; o < 8; o <<= 1) {
            int y = __shfl_up_sync(0xFFFFFFFFu, s, o);
            if (l >= o) s += y;
        }
        if (l < 8) wsum[l] = s;
    }
    __syncthreads();
    int excl = x - v + (w > 0 ? wsum[w - 1] : 0);
    if (i < NN) g_rowptr[i] = excl;
    if (t == 255) g_bsum[blockIdx.x] = excl + v;
}

__global__ void k_scanB() {
    __shared__ int wsum[8];
    const int t = threadIdx.x;            // 256
    const int l = t & 31, w = t >> 5;
    int v = (t < NB) ? g_bsum[t] : 0;
    int x = v;
    #pragma unroll
    for (int o = 1; o < 32; o <<= 1) {
        int y = __shfl_up_sync(0xFFFFFFFFu, x, o);
        if (l >= o) x += y;
    }
    if (l == 31) wsum[w] = x;
    __syncthreads();
    if (w == 0) {
        int s = (l < 8) ? wsum[l] : 0;
        #pragma unroll
        for (int o = 1; o < 8; o <<= 1) {
            int y = __shfl_up_sync(0xFFFFFFFFu, s, o);
            if (l >= o) s += y;
        }
        if (l < 8) wsum[l] = s;
    }
    __syncthreads();
    int excl = x - v + (w > 0 ? wsum[w - 1] : 0);
    if (t < NB) g_bsum[t] = excl;
}

__global__ void k_scanC() {
    const int i = blockIdx.x * SCB + threadIdx.x;
    if (i < NN) {
        int r = g_rowptr[i] + g_bsum[blockIdx.x];
        g_rowptr[i] = r;
        g_fill[i]   = r;
    }
    if (i == 0) g_rowptr[NN] = ET;
}

__global__ void k_place(const int* __restrict__ w) {
    int i = blockIdx.x * blockDim.x + threadIdx.x;
    if (i >= ET) return;
    int s, d;
    if (i < EE) {
        if (g_is64) { s = w[2 * i]; d = w[2 * EE + 2 * i]; }
        else        { s = w[i];     d = w[EE + i]; }
    } else {
        s = d = i - EE;
    }
    int pos = atomicAdd(&g_fill[d], 1);
    g_csrc[pos] = s;
}

// ---------------- 3xTF32 tensor-core GEMM ------------------------------------
// BM=128, BK=16, 256 threads (8 warps). Warp grid WARPS_M x WARPS_N.
// Smem holds tf32 hi/lo planes; D = Ahi*Bhi + Ahi*Blo + Alo*Bhi (fp32-grade).
// ACT: apply elu(a + bias[kcol]) to A elements on load.
template <int BN, int WARPS_M, int WARPS_N, bool ACT>
__device__ __forceinline__ void gemm_mma_body(const float* __restrict__ A,
                                              const float* __restrict__ B,
                                              float* __restrict__ C,
                                              int M, int Nc, int K,
                                              const float* __restrict__ bias) {
    constexpr int BM = 128, BK = 16;
    constexpr int WTM = BM / WARPS_M;        // warp tile rows
    constexpr int WTN = BN / WARPS_N;        // warp tile cols
    constexpr int MF = WTM / 16;             // m16 frags per warp
    constexpr int NF = WTN / 8;              // n8 frags per warp
    constexpr int BMP = BM + 8, BNP = BN + 8;
    constexpr int NB4 = (BK * BN / 4) / 256; // B float4 loads per thread

    __shared__ uint32_t Ah[BK][BMP], Al[BK][BMP];
    __shared__ uint32_t Bh[BK][BNP], Bl[BK][BNP];

    const int t = threadIdx.x;
    const int w = t >> 5, lane = t & 31;
    const int g = lane >> 2, tig = lane & 3;
    const int wm = w / WARPS_N, wn = w % WARPS_N;
    const int m0 = blockIdx.y * BM, n0 = blockIdx.x * BN;

    // A staging: thread covers idx = 2t, 2t+1; row = idx/4 (0..127), kq = (idx%4)*4
    const int ar0 = (2 * t) / 4,     ak0 = ((2 * t)     & 3) * 4;
    const int ar1 = (2 * t + 1) / 4, ak1 = ((2 * t + 1) & 3) * 4;

    float4 acc[MF][NF];
    #pragma unroll
    for (int i = 0; i < MF; i++)
        #pragma unroll
        for (int j = 0; j < NF; j++)
            acc[i][j] = make_float4(0.f, 0.f, 0.f, 0.f);

    float4 av0, av1, bv[NB4];
    const int KT = K / BK;

    auto ldA = [&](int k0, int row, int kq) -> float4 {
        int m = m0 + row;
        float4 v = make_float4(0.f, 0.f, 0.f, 0.f);
        if (m < M) {
            v = *(const float4*)&A[(size_t)m * K + k0 + kq];
            if (ACT) {
                int kc = k0 + kq;
                v.x = eluf(v.x + bias[kc]);
                v.y = eluf(v.y + bias[kc + 1]);
                v.z = eluf(v.z + bias[kc + 2]);
                v.w = eluf(v.w + bias[kc + 3]);
            }
        }
        return v;
    };
    auto ldB = [&](int k0) {
        #pragma unroll
        for (int j = 0; j < NB4; j++) {
            int idx = t + j * 256;
            int row = idx / (BN / 4), c4 = idx % (BN / 4);
            bv[j] = *(const float4*)&B[(size_t)(k0 + row) * Nc + n0 + c4 * 4];
        }
    };
    auto stA = [&](int row, int kq, float4 v) {
        #pragma unroll
        for (int i = 0; i < 4; i++) {
            float x = (&v.x)[i];
            uint32_t h = tf32hi(x);
            Ah[kq + i][row] = h;
            Al[kq + i][row] = tf32hi(x - __uint_as_float(h));
        }
    };
    auto stB = [&]() {
        #pragma unroll
        for (int j = 0; j < NB4; j++) {
            int idx = t + j * 256;
            int row = idx / (BN / 4), c = (idx % (BN / 4)) * 4;
            #pragma unroll
            for (int i = 0; i < 4; i++) {
                float x = (&bv[j].x)[i];
                uint32_t h = tf32hi(x);
                Bh[row][c + i] = h;
                Bl[row][c + i] = tf32hi(x - __uint_as_float(h));
            }
        }
    };

    // prologue: fetch tile 0
    av0 = ldA(0, ar0, ak0);
    av1 = ldA(0, ar1, ak1);
    ldB(0);

    for (int kt = 0; kt < KT; kt++) {
        stA(ar0, ak0, av0);
        stA(ar1, ak1, av1);
        stB();
        __syncthreads();
        if (kt + 1 < KT) {
            int k0 = (kt + 1) * BK;
            av0 = ldA(k0, ar0, ak0);
            av1 = ldA(k0, ar1, ak1);
            ldB(k0);
        }
        #pragma unroll
        for (int ks = 0; ks < BK; ks += 8) {
            uint32_t bh[NF][2], bl[NF][2];
            #pragma unroll
            for (int nf = 0; nf < NF; nf++) {
                int n = wn * WTN + nf * 8 + g;
                bh[nf][0] = Bh[ks + tig][n];     bh[nf][1] = Bh[ks + tig + 4][n];
                bl[nf][0] = Bl[ks + tig][n];     bl[nf][1] = Bl[ks + tig + 4][n];
            }
            #pragma unroll
            for (int mf = 0; mf < MF; mf++) {
                int r = wm * WTM + mf * 16 + g;
                uint32_t ah0 = Ah[ks + tig][r],     ah1 = Ah[ks + tig][r + 8];
                uint32_t ah2 = Ah[ks + tig + 4][r], ah3 = Ah[ks + tig + 4][r + 8];
                uint32_t al0 = Al[ks + tig][r],     al1 = Al[ks + tig][r + 8];
                uint32_t al2 = Al[ks + tig + 4][r], al3 = Al[ks + tig + 4][r + 8];
                #pragma unroll
                for (int nf = 0; nf < NF; nf++) {
                    mma_tf32(acc[mf][nf], ah0, ah1, ah2, ah3, bh[nf][0], bh[nf][1]);
                    mma_tf32(acc[mf][nf], ah0, ah1, ah2, ah3, bl[nf][0], bl[nf][1]);
                    mma_tf32(acc[mf][nf], al0, al1, al2, al3, bh[nf][0], bh[nf][1]);
                }
            }
        }
        __syncthreads();
    }

    // epilogue: c0,c1 at (r, c..c+1); c2,c3 at (r+8, c..c+1)
    #pragma unroll
    for (int mf = 0; mf < MF; mf++) {
        #pragma unroll
        for (int nf = 0; nf < NF; nf++) {
            int r = m0 + wm * WTM + mf * 16 + g;
            int c = n0 + wn * WTN + nf * 8 + tig * 2;
            if (r < M)
                *(float2*)&C[(size_t)r * Nc + c] = make_float2(acc[mf][nf].x, acc[mf][nf].y);
            if (r + 8 < M)
                *(float2*)&C[(size_t)(r + 8) * Nc + c] = make_float2(acc[mf][nf].z, acc[mf][nf].w);
        }
    }
}

__global__ void __launch_bounds__(256) k_gemm1(const float* __restrict__ x,
                                               const float* __restrict__ W1) {
    gemm_mma_body<128, 2, 4, false>(x, W1, g_h1, NN, F1, INDIM, nullptr);
}
// A = elu(g_out1 + b1) fused on load
__global__ void __launch_bounds__(256) k_gemm2(const float* __restrict__ W2,
                                               const float* __restrict__ b1) {
    gemm_mma_body<64, 4, 2, true>(g_out1, W2, g_g2, NN, HIDC, F1, b1);
}

// ---------------- attention coefficients ------------------------------------
__global__ void k_attn1(const float* __restrict__ a_src, const float* __restrict__ a_dst) {
    __shared__ float sa[F1], sd[F1];
    int t = threadIdx.x;                 // 256 threads
    sa[t] = a_src[t]; sd[t] = a_dst[t];
    __syncthreads();
    int w = t >> 5, l = t & 31;
    int n = blockIdx.x * 8 + w;
    if (n >= NN) return;
    const float4* hp = (const float4*)(g_h1 + (size_t)n * F1);
    float ss = 0.f, ds = 0.f;
    #pragma unroll
    for (int q = 0; q < 2; q++) {
        float4 v = hp[l * 2 + q];
        int b = l * 8 + q * 4;
        ss += v.x * sa[b] + v.y * sa[b + 1] + v.z * sa[b + 2] + v.w * sa[b + 3];
        ds += v.x * sd[b] + v.y * sd[b + 1] + v.z * sd[b + 2] + v.w * sd[b + 3];
    }
    #pragma unroll
    for (int o = 4; o >= 1; o >>= 1) {
        ss += __shfl_xor_sync(0xFFFFFFFFu, ss, o);
        ds += __shfl_xor_sync(0xFFFFFFFFu, ds, o);
    }
    if ((l & 7) == 0) {
        int h = l >> 3;
        g_as1[n * H1N + h] = ss;
        g_ad1[n * H1N + h] = ds;
    }
}

__global__ void k_attn2(const float* __restrict__ a_src, const float* __restrict__ a_dst) {
    __shared__ float sa[HIDC], sd[HIDC];
    int t = threadIdx.x;                 // 256 threads
    if (t < HIDC) { sa[t] = a_src[t]; sd[t] = a_dst[t]; }
    __syncthreads();
    int w = t >> 5, l = t & 31;
    int n = blockIdx.x * 8 + w;
    if (n >= NN) return;
    const float2* hp = (const float2*)(g_g2 + (size_t)n * HIDC);
    float2 v = hp[l];
    float ss = v.x * sa[2 * l] + v.y * sa[2 * l + 1];
    float ds = v.x * sd[2 * l] + v.y * sd[2 * l + 1];
    #pragma unroll
    for (int o = 16; o >= 1; o >>= 1) {
        ss += __shfl_xor_sync(0xFFFFFFFFu, ss, o);
        ds += __shfl_xor_sync(0xFFFFFFFFu, ds, o);
    }
    if (l == 0) { g_as2[n] = ss; g_ad2[n] = ds; }
}

// ---------------- fused CSR gather aggregation, layer 1 ----------------------
// warp per destination node (L2-bandwidth-bound; ~870MB gather is the floor).
__global__ void __launch_bounds__(256) k_agg1() {
    int wid = (blockIdx.x * blockDim.x + threadIdx.x) >> 5;
    int l = threadIdx.x & 31;
    if (wid >= NN) return;
    const int d = wid;
    const int r0 = g_rowptr[d], r1 = g_rowptr[d + 1];
    float4 ad4 = *(const float4*)&g_ad1[d * H1N];
    const bool lo = (l < 16);
    const float ad_a = lo ? ad4.x : ad4.y;
    const float ad_b = lo ? ad4.z : ad4.w;
    float4 acc0 = make_float4(0.f, 0.f, 0.f, 0.f);
    float4 acc1 = make_float4(0.f, 0.f, 0.f, 0.f);
    float sum0 = 0.f, sum1 = 0.f;

    int e = r0;
    for (; e + 4 <= r1; e += 4) {
        const int s0 = g_csrc[e], s1 = g_csrc[e + 1], s2 = g_csrc[e + 2], s3 = g_csrc[e + 3];
        float4 A0 = *(const float4*)&g_as1[s0 * H1N];
        float4 A1 = *(const float4*)&g_as1[s1 * H1N];
        float4 A2 = *(const float4*)&g_as1[s2 * H1N];
        float4 A3 = *(const float4*)&g_as1[s3 * H1N];
        const float4* h0 = (const float4*)(g_h1 + (size_t)s0 * F1);
        const float4* h1 = (const float4*)(g_h1 + (size_t)s1 * F1);
        const float4* h2 = (const float4*)(g_h1 + (size_t)s2 * F1);
        const float4* h3 = (const float4*)(g_h1 + (size_t)s3 * F1);
        float4 u00 = h0[l], u01 = h0[l + 32];
        float4 u10 = h1[l], u11 = h1[l + 32];
        float4 u20 = h2[l], u21 = h2[l + 32];
        float4 u30 = h3[l], u31 = h3[l + 32];

        float e00 = __expf(lrelu02((lo ? A0.x : A0.y) + ad_a));
        float e01 = __expf(lrelu02((lo ? A0.z : A0.w) + ad_b));
        float e10 = __expf(lrelu02((lo ? A1.x : A1.y) + ad_a));
        float e11 = __expf(lrelu02((lo ? A1.z : A1.w) + ad_b));
        float e20 = __expf(lrelu02((lo ? A2.x : A2.y) + ad_a));
        float e21 = __expf(lrelu02((lo ? A2.z : A2.w) + ad_b));
        float e30 = __expf(lrelu02((lo ? A3.x : A3.y) + ad_a));
        float e31 = __expf(lrelu02((lo ? A3.z : A3.w) + ad_b));
        sum0 += (e00 + e10) + (e20 + e30);
        sum1 += (e01 + e11) + (e21 + e31);

        acc0.x = fmaf(e00, u00.x, acc0.x); acc0.y = fmaf(e00, u00.y, acc0.y);
        acc0.z = fmaf(e00, u00.z, acc0.z); acc0.w = fmaf(e00, u00.w, acc0.w);
        acc1.x = fmaf(e01, u01.x, acc1.x); acc1.y = fmaf(e01, u01.y, acc1.y);
        acc1.z = fmaf(e01, u01.z, acc1.z); acc1.w = fmaf(e01, u01.w, acc1.w);
        acc0.x = fmaf(e10, u10.x, acc0.x); acc0.y = fmaf(e10, u10.y, acc0.y);
        acc0.z = fmaf(e10, u10.z, acc0.z); acc0.w = fmaf(e10, u10.w, acc0.w);
        acc1.x = fmaf(e11, u11.x, acc1.x); acc1.y = fmaf(e11, u11.y, acc1.y);
        acc1.z = fmaf(e11, u11.z, acc1.z); acc1.w = fmaf(e11, u11.w, acc1.w);
        acc0.x = fmaf(e20, u20.x, acc0.x); acc0.y = fmaf(e20, u20.y, acc0.y);
        acc0.z = fmaf(e20, u20.z, acc0.z); acc0.w = fmaf(e20, u20.w, acc0.w);
        acc1.x = fmaf(e21, u21.x, acc1.x); acc1.y = fmaf(e21, u21.y, acc1.y);
        acc1.z = fmaf(e21, u21.z, acc1.z); acc1.w = fmaf(e21, u21.w, acc1.w);
        acc0.x = fmaf(e30, u30.x, acc0.x); acc0.y = fmaf(e30, u30.y, acc0.y);
        acc0.z = fmaf(e30, u30.z, acc0.z); acc0.w = fmaf(e30, u30.w, acc0.w);
        acc1.x = fmaf(e31, u31.x, acc1.x); acc1.y = fmaf(e31, u31.y, acc1.y);
        acc1.z = fmaf(e31, u31.z, acc1.z); acc1.w = fmaf(e31, u31.w, acc1.w);
    }
    for (; e < r1; e++) {
        int s = g_csrc[e];
        float4 as4 = *(const float4*)&g_as1[s * H1N];
        float e0 = __expf(lrelu02((lo ? as4.x : as4.y) + ad_a));
        float e1 = __expf(lrelu02((lo ? as4.z : as4.w) + ad_b));
        sum0 += e0; sum1 += e1;
        const float4* hp = (const float4*)(g_h1 + (size_t)s * F1);
        float4 v0 = hp[l], v1 = hp[l + 32];
        acc0.x = fmaf(e0, v0.x, acc0.x); acc0.y = fmaf(e0, v0.y, acc0.y);
        acc0.z = fmaf(e0, v0.z, acc0.z); acc0.w = fmaf(e0, v0.w, acc0.w);
        acc1.x = fmaf(e1, v1.x, acc1.x); acc1.y = fmaf(e1, v1.y, acc1.y);
        acc1.z = fmaf(e1, v1.z, acc1.z); acc1.w = fmaf(e1, v1.w, acc1.w);
    }
    float inv0 = 1.f / (sum0 + 1e-16f);
    float inv1 = 1.f / (sum1 + 1e-16f);
    float4* op = (float4*)(g_out1 + (size_t)d * F1);
    op[l]      = make_float4(acc0.x * inv0, acc0.y * inv0, acc0.z * inv0, acc0.w * inv0);
    op[l + 32] = make_float4(acc1.x * inv1, acc1.y * inv1, acc1.z * inv1, acc1.w * inv1);
}

// ---------------- fused CSR gather aggregation, layer 2 ----------------------
__global__ void __launch_bounds__(256) k_agg2() {
    int wid = (blockIdx.x * blockDim.x + threadIdx.x) >> 5;
    int l = threadIdx.x & 31;
    if (wid >= NN) return;
    const int d = wid;
    const int r0 = g_rowptr[d], r1 = g_rowptr[d + 1];
    const float ad = g_ad2[d];
    float2 acc = make_float2(0.f, 0.f);
    float sum = 0.f;

    int e = r0;
    for (; e + 4 <= r1; e += 4) {
        const int s0 = g_csrc[e], s1 = g_csrc[e + 1], s2 = g_csrc[e + 2], s3 = g_csrc[e + 3];
        float a0 = g_as2[s0], a1 = g_as2[s1], a2 = g_as2[s2], a3 = g_as2[s3];
        float2 v0 = ((const float2*)(g_g2 + (size_t)s0 * HIDC))[l];
        float2 v1 = ((const float2*)(g_g2 + (size_t)s1 * HIDC))[l];
        float2 v2 = ((const float2*)(g_g2 + (size_t)s2 * HIDC))[l];
        float2 v3 = ((const float2*)(g_g2 + (size_t)s3 * HIDC))[l];
        float x0 = __expf(lrelu02(a0 + ad));
        float x1 = __expf(lrelu02(a1 + ad));
        float x2 = __expf(lrelu02(a2 + ad));
        float x3 = __expf(lrelu02(a3 + ad));
        sum += (x0 + x1) + (x2 + x3);
        acc.x = fmaf(x0, v0.x, acc.x); acc.y = fmaf(x0, v0.y, acc.y);
        acc.x = fmaf(x1, v1.x, acc.x); acc.y = fmaf(x1, v1.y, acc.y);
        acc.x = fmaf(x2, v2.x, acc.x); acc.y = fmaf(x2, v2.y, acc.y);
        acc.x = fmaf(x3, v3.x, acc.x); acc.y = fmaf(x3, v3.y, acc.y);
    }
    for (; e < r1; e++) {
        int s = g_csrc[e];
        float ex = __expf(lrelu02(g_as2[s] + ad));
        sum += ex;
        float2 v = ((const float2*)(g_g2 + (size_t)s * HIDC))[l];
        acc.x = fmaf(ex, v.x, acc.x);
        acc.y = fmaf(ex, v.y, acc.y);
    }
    float inv = 1.f / (sum + 1e-16f);
    ((float2*)(g_out2 + (size_t)d * HIDC))[l] = make_float2(acc.x * inv, acc.y * inv);
}

// ---------------- classifier MLP: relu(elu(z+b2)@W3+b3)@W4+b4 ---------------
__global__ void k_mlp(const float* __restrict__ b2,
                      const float* __restrict__ W3, const float* __restrict__ b3,
                      const float* __restrict__ W4, const float* __restrict__ b4,
                      float* __restrict__ out) {
    __shared__ float sW3[64 * 32];
    __shared__ float sb3[32];
    __shared__ float sW4[32 * 2];
    __shared__ float sb4[2];
    __shared__ float sb2[64];
    __shared__ float sz[32][65];
    __shared__ float sh[32][33];
    int t = threadIdx.x;                  // 128 threads, 32 nodes per block
    for (int j = t; j < 2048; j += 128) sW3[j] = W3[j];
    if (t < 32) sb3[t] = b3[t];
    if (t < 64) { sW4[t] = W4[t]; sb2[t] = b2[t]; }
    if (t < 2)  sb4[t] = b4[t];
    __syncthreads();
    int n0 = blockIdx.x * 32;
    for (int j = t; j < 2048; j += 128) {
        int r = j >> 6, c = j & 63;
        int n = n0 + r;
        sz[r][c] = (n < NN) ? eluf(g_out2[(size_t)n * HIDC + c] + sb2[c]) : 0.f;
    }
    __syncthreads();
    for (int j = t; j < 1024; j += 128) {
        int r = j >> 5, hh = j & 31;
        float acc = sb3[hh];
        #pragma unroll
        for (int k = 0; k < 64; k++) acc += sz[r][k] * sW3[k * 32 + hh];
        sh[r][hh] = fmaxf(acc, 0.f);
    }
    __syncthreads();
    if (t < 64) {
        int r = t >> 1, o = t & 1;
        int n = n0 + r;
        if (n < NN) {
            float acc = sb4[o];
            #pragma unroll
            for (int k = 0; k < 32; k++) acc += sh[r][k] * sW4[k * 2 + o];
            out[(size_t)n * 2 + o] = acc;
        }
    }
}

// ---------------- launch -----------------------------------------------------
extern "C" void kernel_launch(void* const* d_in, const int* in_sizes, int n_in,
                              void* d_out, int out_size) {
    const float* x       = (const float*)d_in[0];
    const void*  eidx    = d_in[1];
    const float* W1      = (const float*)d_in[2];
    const float* a_src1  = (const float*)d_in[3];
    const float* a_dst1  = (const float*)d_in[4];
    const float* b1      = (const float*)d_in[5];
    const float* W2      = (const float*)d_in[6];
    const float* a_src2  = (const float*)d_in[7];
    const float* a_dst2  = (const float*)d_in[8];
    const float* b2      = (const float*)d_in[9];
    const float* W3      = (const float*)d_in[10];
    const float* b3      = (const float*)d_in[11];
    const float* W4      = (const float*)d_in[12];
    const float* b4      = (const float*)d_in[13];
    float* out = (float*)d_out;

    // One-time resource init (host objects only; same work every call).
    static cudaStream_t s2 = nullptr;
    static cudaEvent_t evStart = nullptr, evCsr = nullptr;
    if (s2 == nullptr) {
        cudaStreamCreateWithFlags(&s2, cudaStreamNonBlocking);
        cudaEventCreateWithFlags(&evStart, cudaEventDisableTiming);
        cudaEventCreateWithFlags(&evCsr, cudaEventDisableTiming);
    }

    // Fork: CSR build on side stream, overlapped with gemm1+attn1.
    cudaEventRecord(evStart, 0);
    cudaStreamWaitEvent(s2, evStart, 0);

    k_init0<<<(NN + 255) / 256, 256, 0, s2>>>();
    k_detect<<<(EE + 255) / 256, 256, 0, s2>>>((const unsigned int*)eidx);
    k_hist<<<(ET + 255) / 256, 256, 0, s2>>>((const int*)eidx);
    k_scanA<<<NB, 256, 0, s2>>>();
    k_scanB<<<1, 256, 0, s2>>>();
    k_scanC<<<NB, 256, 0, s2>>>();
    k_place<<<(ET + 255) / 256, 256, 0, s2>>>((const int*)eidx);
    cudaEventRecord(evCsr, s2);

    // main stream: feature transform + attention coefficients (independent of CSR)
    k_gemm1<<<dim3(F1 / 128, (NN + 127) / 128), 256>>>(x, W1);
    k_attn1<<<(NN + 7) / 8, 256>>>(a_src1, a_dst1);

    // join before aggregation
    cudaStreamWaitEvent(0, evCsr, 0);
    k_agg1<<<(NN * 32 + 255) / 256, 256>>>();

    // layer 2 (bias+ELU of layer1 fused into gemm2's A load)
    k_gemm2<<<dim3(HIDC / 64, (NN + 127) / 128), 256>>>(W2, b1);
    k_attn2<<<(NN + 7) / 8, 256>>>(a_src2, a_dst2);
    k_agg2<<<(NN * 32 + 255) / 256, 256>>>();

    // classifier (bias+ELU of layer2 fused into MLP input load)
    k_mlp<<<(NN + 31) / 32, 128>>>(b2, W3, b3, W4, b4, out);
}